// round 11
// baseline (speedup 1.0000x reference)
#include <cuda_runtime.h>
#include <cuda_fp16.h>
#include <cstdint>

#define NN 100000
#define EE 1600000
#define GG 512
#define DD 128
#define CC 10
#define EPS 1e-5f
#define SB 1024
#define NSB ((NN + SB - 1) / SB)

typedef unsigned long long u64;

// ---------------- device scratch ----------------
__device__ float   g_h[NN * DD];
__device__ __half2 g_h16a[NN * (DD / 2)];  // double-buffered h (fp16) for gathers
__device__ __half2 g_h16b[NN * (DD / 2)];
__device__ float   g_t[NN];                // sum of ns over in-edges
__device__ float   g_ns[NN];
__device__ float   g_nd[NN];
__device__ int     g_degO[NN];
__device__ int     g_degI[NN];
__device__ int     g_off[NN + 1];
__device__ int     g_cur[NN];
__device__ int     g_esrc[EE];
__device__ int     g_bsum[128];
__device__ int     g_boff[128];
__device__ float   g_sumL[4][DD], g_sqL[4][DD];   // per-layer BN stats
__device__ float   g_hg[GG * DD], g_hg2[GG * DD];
__device__ float   g_psum[DD], g_psq[DD], g_fsum[DD], g_fsq[DD];

// ---------------- f32x2 helpers ----------------
__device__ __forceinline__ u64 pack2(float lo, float hi) {
    u64 r; asm("mov.b64 %0,{%1,%2};" : "=l"(r) : "f"(lo), "f"(hi)); return r;
}
__device__ __forceinline__ void unpack2(u64 v, float& lo, float& hi) {
    asm("mov.b64 {%0,%1},%2;" : "=f"(lo), "=f"(hi) : "l"(v));
}
__device__ __forceinline__ void fma2(u64& d, u64 a, u64 b) {
    asm("fma.rn.f32x2 %0,%1,%2,%0;" : "+l"(d) : "l"(a), "l"(b));
}

// ---------------- init ----------------
__global__ void init_kernel() {
    int i = blockIdx.x * blockDim.x + threadIdx.x;
    if (i < NN) { g_degO[i] = 0; g_degI[i] = 0; g_t[i] = 0.f; }
    if (i < DD) {
        #pragma unroll
        for (int l = 0; l < 4; l++) { g_sumL[l][i] = 0.f; g_sqL[l][i] = 0.f; }
        g_psum[i] = 0.f; g_psq[i] = 0.f;
        g_fsum[i] = 0.f; g_fsq[i] = 0.f;
    }
}

__global__ void degree_kernel(const int* __restrict__ src, const int* __restrict__ dst) {
    int e = blockIdx.x * blockDim.x + threadIdx.x;
    if (e < EE) {
        atomicAdd(&g_degO[src[e]], 1);
        atomicAdd(&g_degI[dst[e]], 1);
    }
}

// ---------------- 3-pass scan over g_degI ----------------
__global__ void scan1_kernel() {
    __shared__ int wsum[8];
    int b = blockIdx.x, tid = threadIdx.x;
    int base = b * SB + tid * 4;
    int s = 0;
    #pragma unroll
    for (int u = 0; u < 4; u++) { int i = base + u; if (i < NN) s += g_degI[i]; }
    int lane = tid & 31, wid = tid >> 5;
    #pragma unroll
    for (int o = 16; o > 0; o >>= 1) s += __shfl_down_sync(0xffffffffu, s, o);
    if (lane == 0) wsum[wid] = s;
    __syncthreads();
    if (tid == 0) {
        int t = 0;
        #pragma unroll
        for (int w = 0; w < 8; w++) t += wsum[w];
        g_bsum[b] = t;
    }
}

__global__ void scan2_kernel() {
    __shared__ int ws[4];
    int tid = threadIdx.x;
    int lane = tid & 31, wid = tid >> 5;
    int v = (tid < NSB) ? g_bsum[tid] : 0;
    int x = v;
    #pragma unroll
    for (int o = 1; o < 32; o <<= 1) {
        int y = __shfl_up_sync(0xffffffffu, x, o);
        if (lane >= o) x += y;
    }
    if (lane == 31) ws[wid] = x;
    __syncthreads();
    if (tid == 0) {
        int c = 0;
        #pragma unroll
        for (int w = 0; w < 4; w++) { int t = ws[w]; ws[w] = c; c += t; }
    }
    __syncthreads();
    int excl = x - v + ws[wid];
    if (tid < NSB) g_boff[tid] = excl;
    if (tid == 0) g_off[NN] = EE;
}

__global__ void scan3_kernel() {
    __shared__ int wsum[8];
    int b = blockIdx.x, tid = threadIdx.x;
    int base = b * SB + tid * 4;
    int v[4];
    #pragma unroll
    for (int u = 0; u < 4; u++) {
        int i = base + u;
        v[u] = (i < NN) ? g_degI[i] : 0;
    }
    int tot = v[0] + v[1] + v[2] + v[3];
    int lane = tid & 31, wid = tid >> 5;
    int x = tot;
    #pragma unroll
    for (int o = 1; o < 32; o <<= 1) {
        int y = __shfl_up_sync(0xffffffffu, x, o);
        if (lane >= o) x += y;
    }
    if (lane == 31) wsum[wid] = x;
    __syncthreads();
    if (wid == 0 && lane < 8) {
        int w = wsum[lane];
        int xx = w;
        #pragma unroll
        for (int o = 1; o < 8; o <<= 1) {
            int y = __shfl_up_sync(0xffu, xx, o);
            if (lane >= o) xx += y;
        }
        wsum[lane] = xx - w;
    }
    __syncthreads();
    int p = x - tot + wsum[wid] + g_boff[b];
    #pragma unroll
    for (int u = 0; u < 4; u++) {
        int i = base + u;
        if (i < NN) {
            g_off[i] = p; g_cur[i] = p; p += v[u];
            g_nd[i] = rsqrtf((float)max(v[u], 1));
            g_ns[i] = rsqrtf((float)max(g_degO[i], 1));
        }
    }
}

// fill CSR + accumulate sum of ns[src] per dst
__global__ void fill_kernel(const int* __restrict__ src, const int* __restrict__ dst) {
    int e = blockIdx.x * blockDim.x + threadIdx.x;
    if (e < EE) {
        int s = src[e], d = dst[e];
        int p = atomicAdd(&g_cur[d], 1);
        g_esrc[p] = s;
        atomicAdd(&g_t[d], g_ns[s]);
    }
}

// ---------------- BN stats over external input (feat layer only) ----------------
__global__ void stats_in_kernel(const float* __restrict__ x) {
    int c = threadIdx.x;
    float s = 0.f, q = 0.f;
    for (int r = blockIdx.x; r < NN; r += gridDim.x) {
        float v = x[r * DD + c];
        s += v; q += v * v;
    }
    atomicAdd(&g_sumL[0][c], s);
    atomicAdd(&g_sqL[0][c], q);
}

// ---------------- fused layer kernel ----------------
// Per block (128 rows): inline BN fold + bv@W, [agg phase | X load], FFMA2 GEMM,
// epilogue: bias + t*cvec + relu (+residual), h16 out, next-layer stats.
// Dynamic smem (floats):
//   Xs   [0, 16896)   = X tile [128][132]
//   Ws   [16896, 20992)
//   sa   [20992..), sbv [21120..), sbias [21248..), scvec [21376..), red [21504, 21760)
#define XS_STRIDE 132
#define SMF_WS   16896
#define SMF_SA   20992
#define SMF_SBV  21120
#define SMF_SBI  21248
#define SMF_SCV  21376
#define SMF_RED  21504
#define GEMM_SMEM_B (21760 * 4)

template <bool FEAT, bool STATS, bool WH16, int BIN>
__global__ void __launch_bounds__(256, 2)
gemm_fused(const float* __restrict__ Xin,
           const float* __restrict__ bng, const float* __restrict__ bnb,
           const float* __restrict__ W, const float* __restrict__ addb,
           int layer) {
    extern __shared__ float sm[];
    float* Xs    = sm;
    float* Ws    = sm + SMF_WS;
    float* sa    = sm + SMF_SA;
    float* sbv   = sm + SMF_SBV;
    float* sbias = sm + SMF_SBI;
    float* scvec = sm + SMF_SCV;
    float* red   = sm + SMF_RED;
    int tid = threadIdx.x;
    int m0g = blockIdx.x * 128;
    int tx = tid & 15, ty = tid >> 4;
    int mm = ty * 8, nn = tx * 8;
    int lane = tid & 31, wid = tid >> 5;

    // phase A: BN finalize
    if (tid < 128) {
        float m = g_sumL[layer][tid] * (1.0f / NN);
        float v = g_sqL[layer][tid] * (1.0f / NN) - m * m;
        float a = bng[tid] * rsqrtf(v + EPS);
        sa[tid] = a;
        sbv[tid] = bnb[tid] - m * a;
    }
    __syncthreads();
    // phase B: bv @ W (column sums)
    {
        int n = tid & 127, part = tid >> 7;
        float s = 0.f;
        #pragma unroll 8
        for (int k = part * 64; k < part * 64 + 64; k++)
            s += sbv[k] * W[k * DD + n];
        red[part * 128 + n] = s;
    }
    __syncthreads();
    if (tid < 128) {
        float t = red[tid] + red[128 + tid];
        if (FEAT) { sbias[tid] = addb[tid] + t; }
        else      { sbias[tid] = addb[tid]; scvec[tid] = t; }
    }

    // phase C: fill X tile (agg or direct load)
    if (FEAT) {
        #pragma unroll 4
        for (int r = 0; r < 16; r++) {
            int row = wid * 16 + r;
            int gr = m0g + row;
            float4 v = make_float4(0.f, 0.f, 0.f, 0.f);
            if (gr < NN) v = *(const float4*)(Xin + gr * DD + 4 * lane);
            *(float4*)&Xs[row * XS_STRIDE + 4 * lane] = v;
        }
    } else {
        const uint2* __restrict__ h2 =
            (const uint2*)(BIN == 0 ? g_h16a : g_h16b);
        for (int r = 0; r < 16; r++) {
            int row = wid * 16 + r;
            int node = m0g + row;
            float a0 = 0.f, a1 = 0.f, a2 = 0.f, a3 = 0.f;
            if (node < NN) {
                int beg = g_off[node], end = g_off[node + 1];
                for (int e = beg; e < end; e++) {
                    int s = g_esrc[e];
                    float w = g_ns[s];
                    uint2 hv = h2[(size_t)s * 32 + lane];
                    float2 f0 = __half22float2(*(__half2*)&hv.x);
                    float2 f1 = __half22float2(*(__half2*)&hv.y);
                    a0 += f0.x * w; a1 += f0.y * w;
                    a2 += f1.x * w; a3 += f1.y * w;
                }
                float nd = g_nd[node];
                a0 *= nd; a1 *= nd; a2 *= nd; a3 *= nd;
            }
            *(float4*)&Xs[row * XS_STRIDE + 4 * lane] = make_float4(a0, a1, a2, a3);
        }
    }
    __syncthreads();

    // mainloop (R9-proven FFMA2 structure; W chunked, X resident)
    u64 acc[8][4];
    #pragma unroll
    for (int i = 0; i < 8; i++)
        #pragma unroll
        for (int j = 0; j < 4; j++) acc[i][j] = pack2(0.f, 0.f);

    for (int kc = 0; kc < 4; kc++) {
        int k0 = kc * 32;
        #pragma unroll
        for (int it = 0; it < 4; it++) {
            int idx = tid + it * 256;
            int kr = idx >> 5, nq = idx & 31;
            int k = k0 + kr;
            float4 w = *(const float4*)(W + k * DD + nq * 4);
            float a = sa[k];
            w.x *= a; w.y *= a; w.z *= a; w.w *= a;
            *(float4*)&Ws[kr * 128 + nq * 4] = w;
        }
        __syncthreads();
        #pragma unroll
        for (int k = 0; k < 32; k++) {
            int kk = k0 + k;
            float xr[8];
            #pragma unroll
            for (int i = 0; i < 8; i++) xr[i] = Xs[(mm + i) * XS_STRIDE + kk];
            ulonglong2 wa = *(const ulonglong2*)&Ws[k * 128 + nn];
            ulonglong2 wb = *(const ulonglong2*)&Ws[k * 128 + nn + 4];
            u64 w0 = wa.x, w1 = wa.y, w2 = wb.x, w3 = wb.y;
            #pragma unroll
            for (int i = 0; i < 8; i++) {
                u64 xp = pack2(xr[i], xr[i]);
                fma2(acc[i][0], xp, w0);
                fma2(acc[i][1], xp, w1);
                fma2(acc[i][2], xp, w2);
                fma2(acc[i][3], xp, w3);
            }
        }
        __syncthreads();
    }

    // epilogue
    __half2* __restrict__ h16o = (BIN == 0 ? g_h16b : g_h16a);
    float colsum[8], colsq[8];
    #pragma unroll
    for (int j = 0; j < 8; j++) { colsum[j] = 0.f; colsq[j] = 0.f; }

    #pragma unroll
    for (int i = 0; i < 8; i++) {
        int row = m0g + mm + i;
        bool ok = row < NN;
        float tval = (!FEAT && ok) ? g_t[row] * g_nd[row] : 0.f;
        #pragma unroll
        for (int jp = 0; jp < 4; jp++) {
            float v0, v1;
            unpack2(acc[i][jp], v0, v1);
            int n0 = nn + jp * 2;
            float va = v0 + sbias[n0];
            float vb = v1 + sbias[n0 + 1];
            if (!FEAT) { va += tval * scvec[n0]; vb += tval * scvec[n0 + 1]; }
            va = fmaxf(va, 0.f); vb = fmaxf(vb, 0.f);
            if (ok) {
                float oa, ob;
                if (!FEAT) {   // residual
                    oa = g_h[row * DD + n0] + va;
                    ob = g_h[row * DD + n0 + 1] + vb;
                } else { oa = va; ob = vb; }
                g_h[row * DD + n0] = oa;
                g_h[row * DD + n0 + 1] = ob;
                if (WH16)
                    h16o[(row * DD + n0) >> 1] = __floats2half2_rn(oa, ob);
                if (STATS) {
                    colsum[jp * 2] += oa;     colsq[jp * 2] += oa * oa;
                    colsum[jp * 2 + 1] += ob; colsq[jp * 2 + 1] += ob * ob;
                }
            }
        }
    }

    if (STATS) {
        float* sred = Ws;           // 2048 floats
        float* sqd  = Ws + 2048;    // 2048 floats
        #pragma unroll
        for (int j = 0; j < 8; j++) {
            sred[ty * 128 + nn + j] = colsum[j];
            sqd[ty * 128 + nn + j]  = colsq[j];
        }
        __syncthreads();
        if (tid < 128) {
            float s = 0.f, q = 0.f;
            #pragma unroll
            for (int t2 = 0; t2 < 16; t2++) {
                s += sred[t2 * 128 + tid];
                q += sqd[t2 * 128 + tid];
            }
            atomicAdd(&g_sumL[layer + 1][tid], s);
            atomicAdd(&g_sqL[layer + 1][tid], q);
        }
    }
}

// ---------------- pooling + head ----------------
__global__ void pool_kernel(const int* __restrict__ gid) {
    int g = blockIdx.x, c = threadIdx.x;
    int lo = 0, hi = NN;
    while (lo < hi) { int mid = (lo + hi) >> 1; if (gid[mid] < g) lo = mid + 1; else hi = mid; }
    int s0 = lo;
    lo = s0; hi = NN;
    while (lo < hi) { int mid = (lo + hi) >> 1; if (gid[mid] < g + 1) lo = mid + 1; else hi = mid; }
    int s1 = lo;
    float s = 0.f;
    for (int r = s0; r < s1; r++) s += g_h[r * DD + c];
    g_hg[g * DD + c] = s;
    atomicAdd(&g_psum[c], s);
    atomicAdd(&g_psq[c], s * s);
}

__global__ void fc_kernel(const float* __restrict__ W, const float* __restrict__ bias,
                          const float* __restrict__ gma, const float* __restrict__ bta) {
    __shared__ float x[DD];
    int r = blockIdx.x, c = threadIdx.x;
    float m = g_psum[c] * (1.0f / GG);
    float v = g_psq[c] * (1.0f / GG) - m * m;
    float a = gma[c] * rsqrtf(v + EPS);
    float bv = bta[c] - m * a;
    x[c] = g_hg[r * DD + c] * a + bv;
    __syncthreads();
    float s = bias[c];
    #pragma unroll 8
    for (int k = 0; k < DD; k++) s += x[k] * W[k * DD + c];
    float o = fmaxf(s, 0.f);
    g_hg2[r * DD + c] = o;
    atomicAdd(&g_fsum[c], o);
    atomicAdd(&g_fsq[c], o * o);
}

__global__ void cls_kernel(const float* __restrict__ W, const float* __restrict__ bias,
                           const float* __restrict__ gma, const float* __restrict__ bta,
                           float* __restrict__ out) {
    __shared__ float x[DD];
    int r = blockIdx.x, c = threadIdx.x;
    float m = g_fsum[c] * (1.0f / GG);
    float v = g_fsq[c] * (1.0f / GG) - m * m;
    float a = gma[c] * rsqrtf(v + EPS);
    float bv = bta[c] - m * a;
    x[c] = g_hg2[r * DD + c] * a + bv;
    __syncthreads();
    if (c < CC) {
        float s = bias[c];
        for (int k = 0; k < DD; k++) s += x[k] * W[k * CC + c];
        out[r * CC + c] = s;
    }
}

// ---------------- launch ----------------
extern "C" void kernel_launch(void* const* d_in, const int* in_sizes, int n_in,
                              void* d_out, int out_size) {
    const float* h_in      = (const float*)d_in[0];
    const float* bn_feat_g = (const float*)d_in[1];
    const float* bn_feat_b = (const float*)d_in[2];
    const float* feat_W    = (const float*)d_in[3];
    const float* feat_b    = (const float*)d_in[4];
    const float* conv_bn_g = (const float*)d_in[5];
    const float* conv_bn_b = (const float*)d_in[6];
    const float* conv_W    = (const float*)d_in[7];
    const float* conv_b    = (const float*)d_in[8];
    const float* fc_bn_g   = (const float*)d_in[9];
    const float* fc_bn_b   = (const float*)d_in[10];
    const float* fc_W      = (const float*)d_in[11];
    const float* fc_b      = (const float*)d_in[12];
    const float* bn_hid_g  = (const float*)d_in[13];
    const float* bn_hid_b  = (const float*)d_in[14];
    const float* cls_W     = (const float*)d_in[15];
    const float* cls_b     = (const float*)d_in[16];
    const int*   src       = (const int*)d_in[17];
    const int*   dst       = (const int*)d_in[18];
    const int*   gid       = (const int*)d_in[19];
    float* out = (float*)d_out;

    const int nblkN = (NN + 255) / 256;
    const int nblkE = (EE + 255) / 256;
    const int gemmBlks = (NN + 127) / 128;

    static cudaStream_t s2 = nullptr;
    static cudaEvent_t e0, eFill;
    if (s2 == nullptr) {
        cudaStreamCreateWithFlags(&s2, cudaStreamNonBlocking);
        cudaEventCreateWithFlags(&e0, cudaEventDisableTiming);
        cudaEventCreateWithFlags(&eFill, cudaEventDisableTiming);
        cudaFuncSetAttribute(gemm_fused<true, true, true, 1>,
                             cudaFuncAttributeMaxDynamicSharedMemorySize, GEMM_SMEM_B);
        cudaFuncSetAttribute(gemm_fused<false, true, true, 0>,
                             cudaFuncAttributeMaxDynamicSharedMemorySize, GEMM_SMEM_B);
        cudaFuncSetAttribute(gemm_fused<false, true, true, 1>,
                             cudaFuncAttributeMaxDynamicSharedMemorySize, GEMM_SMEM_B);
        cudaFuncSetAttribute(gemm_fused<false, false, false, 0>,
                             cudaFuncAttributeMaxDynamicSharedMemorySize, GEMM_SMEM_B);
    }
    cudaStream_t ms = 0;   // capture (main) stream

    // root
    init_kernel<<<nblkN, 256, 0, ms>>>();
    cudaEventRecord(e0, ms);

    // branch B (side stream): graph structure
    cudaStreamWaitEvent(s2, e0, 0);
    degree_kernel<<<nblkE, 256, 0, s2>>>(src, dst);
    scan1_kernel<<<NSB, 256, 0, s2>>>();
    scan2_kernel<<<1, 128, 0, s2>>>();
    scan3_kernel<<<NSB, 256, 0, s2>>>();
    fill_kernel<<<nblkE, 256, 0, s2>>>(src, dst);
    cudaEventRecord(eFill, s2);

    // branch A (main stream): feat layer (no graph deps)
    stats_in_kernel<<<512, DD, 0, ms>>>(h_in);
    gemm_fused<true, true, true, 1><<<gemmBlks, 256, GEMM_SMEM_B, ms>>>(
        h_in, bn_feat_g, bn_feat_b, feat_W, feat_b, 0);

    // conv layers (fused agg+gemm), need CSR
    cudaStreamWaitEvent(ms, eFill, 0);
    gemm_fused<false, true, true, 0><<<gemmBlks, 256, GEMM_SMEM_B, ms>>>(
        nullptr, conv_bn_g + 0 * DD, conv_bn_b + 0 * DD, conv_W + 0 * DD * DD,
        conv_b + 0 * DD, 1);
    gemm_fused<false, true, true, 1><<<gemmBlks, 256, GEMM_SMEM_B, ms>>>(
        nullptr, conv_bn_g + 1 * DD, conv_bn_b + 1 * DD, conv_W + 1 * DD * DD,
        conv_b + 1 * DD, 2);
    gemm_fused<false, false, false, 0><<<gemmBlks, 256, GEMM_SMEM_B, ms>>>(
        nullptr, conv_bn_g + 2 * DD, conv_bn_b + 2 * DD, conv_W + 2 * DD * DD,
        conv_b + 2 * DD, 3);

    // pooling + head
    pool_kernel<<<GG, DD, 0, ms>>>(gid);
    fc_kernel<<<GG, DD, 0, ms>>>(fc_W, fc_b, fc_bn_g, fc_bn_b);
    cls_kernel<<<GG, DD, 0, ms>>>(cls_W, cls_b, bn_hid_g, bn_hid_b, out);
}

// round 12
// speedup vs baseline: 1.0060x; 1.0060x over previous
#include <cuda_runtime.h>
#include <cuda_fp16.h>
#include <cstdint>

#define NN 100000
#define EE 1600000
#define GG 512
#define DD 128
#define CC 10
#define EPS 1e-5f
#define SB 1024
#define NSB ((NN + SB - 1) / SB)

typedef unsigned long long u64;

// ---------------- device scratch ----------------
__device__ float   g_h[NN * DD];
__device__ __half2 g_h16a[NN * (DD / 2)];  // double-buffered h (fp16) for gathers
__device__ __half2 g_h16b[NN * (DD / 2)];
__device__ float   g_t[NN];                // sum of ns over in-edges
__device__ float   g_ns[NN];
__device__ float   g_nd[NN];
__device__ int     g_degO[NN];
__device__ int     g_degI[NN];
__device__ int     g_off[NN + 1];
__device__ int     g_cur[NN];
__device__ int     g_esrc[EE];
__device__ int     g_bsum[128];
__device__ int     g_boff[128];
__device__ float   g_sumL[4][DD], g_sqL[4][DD];   // per-layer BN stats
__device__ float   g_hg[GG * DD], g_hg2[GG * DD];
__device__ float   g_psum[DD], g_psq[DD], g_fsum[DD], g_fsq[DD];

// ---------------- f32x2 helpers ----------------
__device__ __forceinline__ u64 pack2(float lo, float hi) {
    u64 r; asm("mov.b64 %0,{%1,%2};" : "=l"(r) : "f"(lo), "f"(hi)); return r;
}
__device__ __forceinline__ void unpack2(u64 v, float& lo, float& hi) {
    asm("mov.b64 {%0,%1},%2;" : "=f"(lo), "=f"(hi) : "l"(v));
}
__device__ __forceinline__ void fma2(u64& d, u64 a, u64 b) {
    asm("fma.rn.f32x2 %0,%1,%2,%0;" : "+l"(d) : "l"(a), "l"(b));
}

// ---------------- init ----------------
__global__ void init_kernel() {
    int i = blockIdx.x * blockDim.x + threadIdx.x;
    if (i < NN) { g_degO[i] = 0; g_degI[i] = 0; g_t[i] = 0.f; }
    if (i < DD) {
        #pragma unroll
        for (int l = 0; l < 4; l++) { g_sumL[l][i] = 0.f; g_sqL[l][i] = 0.f; }
        g_psum[i] = 0.f; g_psq[i] = 0.f;
        g_fsum[i] = 0.f; g_fsq[i] = 0.f;
    }
}

__global__ void degree_kernel(const int* __restrict__ src, const int* __restrict__ dst) {
    int e = blockIdx.x * blockDim.x + threadIdx.x;
    if (e < EE) {
        atomicAdd(&g_degO[src[e]], 1);
        atomicAdd(&g_degI[dst[e]], 1);
    }
}

// ---------------- 3-pass scan over g_degI ----------------
__global__ void scan1_kernel() {
    __shared__ int wsum[8];
    int b = blockIdx.x, tid = threadIdx.x;
    int base = b * SB + tid * 4;
    int s = 0;
    #pragma unroll
    for (int u = 0; u < 4; u++) { int i = base + u; if (i < NN) s += g_degI[i]; }
    int lane = tid & 31, wid = tid >> 5;
    #pragma unroll
    for (int o = 16; o > 0; o >>= 1) s += __shfl_down_sync(0xffffffffu, s, o);
    if (lane == 0) wsum[wid] = s;
    __syncthreads();
    if (tid == 0) {
        int t = 0;
        #pragma unroll
        for (int w = 0; w < 8; w++) t += wsum[w];
        g_bsum[b] = t;
    }
}

__global__ void scan2_kernel() {
    __shared__ int ws[4];
    int tid = threadIdx.x;
    int lane = tid & 31, wid = tid >> 5;
    int v = (tid < NSB) ? g_bsum[tid] : 0;
    int x = v;
    #pragma unroll
    for (int o = 1; o < 32; o <<= 1) {
        int y = __shfl_up_sync(0xffffffffu, x, o);
        if (lane >= o) x += y;
    }
    if (lane == 31) ws[wid] = x;
    __syncthreads();
    if (tid == 0) {
        int c = 0;
        #pragma unroll
        for (int w = 0; w < 4; w++) { int t = ws[w]; ws[w] = c; c += t; }
    }
    __syncthreads();
    int excl = x - v + ws[wid];
    if (tid < NSB) g_boff[tid] = excl;
    if (tid == 0) g_off[NN] = EE;
}

__global__ void scan3_kernel() {
    __shared__ int wsum[8];
    int b = blockIdx.x, tid = threadIdx.x;
    int base = b * SB + tid * 4;
    int v[4];
    #pragma unroll
    for (int u = 0; u < 4; u++) {
        int i = base + u;
        v[u] = (i < NN) ? g_degI[i] : 0;
    }
    int tot = v[0] + v[1] + v[2] + v[3];
    int lane = tid & 31, wid = tid >> 5;
    int x = tot;
    #pragma unroll
    for (int o = 1; o < 32; o <<= 1) {
        int y = __shfl_up_sync(0xffffffffu, x, o);
        if (lane >= o) x += y;
    }
    if (lane == 31) wsum[wid] = x;
    __syncthreads();
    if (wid == 0 && lane < 8) {
        int w = wsum[lane];
        int xx = w;
        #pragma unroll
        for (int o = 1; o < 8; o <<= 1) {
            int y = __shfl_up_sync(0xffu, xx, o);
            if (lane >= o) xx += y;
        }
        wsum[lane] = xx - w;
    }
    __syncthreads();
    int p = x - tot + wsum[wid] + g_boff[b];
    #pragma unroll
    for (int u = 0; u < 4; u++) {
        int i = base + u;
        if (i < NN) {
            g_off[i] = p; g_cur[i] = p; p += v[u];
            g_nd[i] = rsqrtf((float)max(v[u], 1));
            g_ns[i] = rsqrtf((float)max(g_degO[i], 1));
        }
    }
}

// fill CSR + accumulate sum of ns[src] per dst
__global__ void fill_kernel(const int* __restrict__ src, const int* __restrict__ dst) {
    int e = blockIdx.x * blockDim.x + threadIdx.x;
    if (e < EE) {
        int s = src[e], d = dst[e];
        int p = atomicAdd(&g_cur[d], 1);
        g_esrc[p] = s;
        atomicAdd(&g_t[d], g_ns[s]);
    }
}

// ---------------- BN stats over external input (feat layer only) ----------------
__global__ void stats_in_kernel(const float* __restrict__ x) {
    int c = threadIdx.x;
    float s = 0.f, q = 0.f;
    for (int r = blockIdx.x; r < NN; r += gridDim.x) {
        float v = x[r * DD + c];
        s += v; q += v * v;
    }
    atomicAdd(&g_sumL[0][c], s);
    atomicAdd(&g_sqL[0][c], q);
}

// ---------------- fused layer kernel v2 (R9 conflict-free mainloop layout) ----------------
// smem floats:
//   Xst [0, 16512)        transposed X tile [128 k][129]
//   Ws  [16512, 20608)    staged W chunk [32][128]
//   sa [20608..), sbv [20736..), sbias [20864..), scvec [20992..), red [21120, 21376)
#define XT 129
#define SMF_WS   16512
#define SMF_SA   20608
#define SMF_SBV  20736
#define SMF_SBI  20864
#define SMF_SCV  20992
#define SMF_RED  21120
#define GEMM_SMEM_B (21376 * 4)

template <bool FEAT, bool STATS, bool WH16, int BIN>
__global__ void __launch_bounds__(256, 2)
gemm_fused(const float* __restrict__ Xin,
           const float* __restrict__ bng, const float* __restrict__ bnb,
           const float* __restrict__ W, const float* __restrict__ addb,
           int layer) {
    extern __shared__ float sm[];
    float* Xst   = sm;
    float* Ws    = sm + SMF_WS;
    float* sa    = sm + SMF_SA;
    float* sbv   = sm + SMF_SBV;
    float* sbias = sm + SMF_SBI;
    float* scvec = sm + SMF_SCV;
    float* red   = sm + SMF_RED;
    int tid = threadIdx.x;
    int m0g = blockIdx.x * 128;
    int tx = tid & 15, ty = tid >> 4;
    int mm = ty * 8, nn = tx * 8;
    int lane = tid & 31, wid = tid >> 5;

    // phase A: BN finalize
    if (tid < 128) {
        float m = g_sumL[layer][tid] * (1.0f / NN);
        float v = g_sqL[layer][tid] * (1.0f / NN) - m * m;
        float a = bng[tid] * rsqrtf(v + EPS);
        sa[tid] = a;
        sbv[tid] = bnb[tid] - m * a;
    }
    __syncthreads();
    // phase B: bv @ W (column sums)
    {
        int n = tid & 127, part = tid >> 7;
        float s = 0.f;
        #pragma unroll 8
        for (int k = part * 64; k < part * 64 + 64; k++)
            s += sbv[k] * W[k * DD + n];
        red[part * 128 + n] = s;
    }

    // phase C: fill X tile TRANSPOSED (agg or direct load)
    if (FEAT) {
        #pragma unroll
        for (int it = 0; it < 16; it++) {
            int idx = tid + it * 256;
            int row = idx >> 5, kq = idx & 31;
            int gr = m0g + row;
            float4 v = make_float4(0.f, 0.f, 0.f, 0.f);
            if (gr < NN) v = *(const float4*)(Xin + gr * DD + kq * 4);
            Xst[(kq * 4 + 0) * XT + row] = v.x;
            Xst[(kq * 4 + 1) * XT + row] = v.y;
            Xst[(kq * 4 + 2) * XT + row] = v.z;
            Xst[(kq * 4 + 3) * XT + row] = v.w;
        }
    } else {
        const uint2* __restrict__ h2 =
            (const uint2*)(BIN == 0 ? g_h16a : g_h16b);
        for (int r = 0; r < 16; r++) {
            int row = wid * 16 + r;
            int node = m0g + row;
            float a0 = 0.f, a1 = 0.f, a2 = 0.f, a3 = 0.f;
            if (node < NN) {
                int beg = g_off[node], end = g_off[node + 1];
                for (int e = beg; e < end; e++) {
                    int s = g_esrc[e];
                    float w = g_ns[s];
                    uint2 hv = h2[(size_t)s * 32 + lane];
                    float2 f0 = __half22float2(*(__half2*)&hv.x);
                    float2 f1 = __half22float2(*(__half2*)&hv.y);
                    a0 += f0.x * w; a1 += f0.y * w;
                    a2 += f1.x * w; a3 += f1.y * w;
                }
                float nd = g_nd[node];
                a0 *= nd; a1 *= nd; a2 *= nd; a3 *= nd;
            }
            Xst[(4 * lane + 0) * XT + row] = a0;
            Xst[(4 * lane + 1) * XT + row] = a1;
            Xst[(4 * lane + 2) * XT + row] = a2;
            Xst[(4 * lane + 3) * XT + row] = a3;
        }
    }
    __syncthreads();
    if (tid < 128) {
        float t = red[tid] + red[128 + tid];
        if (FEAT) { sbias[tid] = addb[tid] + t; }
        else      { sbias[tid] = addb[tid]; scvec[tid] = t; }
    }

    // mainloop: R9-proven access patterns (X resident transposed, W per-kc)
    u64 acc[8][4];
    #pragma unroll
    for (int i = 0; i < 8; i++)
        #pragma unroll
        for (int j = 0; j < 4; j++) acc[i][j] = pack2(0.f, 0.f);

    for (int kc = 0; kc < 4; kc++) {
        int k0 = kc * 32;
        #pragma unroll
        for (int it = 0; it < 4; it++) {
            int idx = tid + it * 256;
            int kr = idx >> 5, nq = idx & 31;
            int k = k0 + kr;
            float4 w = *(const float4*)(W + k * DD + nq * 4);
            float a = sa[k];
            w.x *= a; w.y *= a; w.z *= a; w.w *= a;
            *(float4*)&Ws[kr * 128 + nq * 4] = w;
        }
        __syncthreads();
        #pragma unroll
        for (int k = 0; k < 32; k++) {
            float xr[8];
            #pragma unroll
            for (int i = 0; i < 8; i++) xr[i] = Xst[(k0 + k) * XT + mm + i];
            ulonglong2 wa = *(const ulonglong2*)&Ws[k * 128 + nn];
            ulonglong2 wb = *(const ulonglong2*)&Ws[k * 128 + nn + 4];
            u64 w0 = wa.x, w1 = wa.y, w2 = wb.x, w3 = wb.y;
            #pragma unroll
            for (int i = 0; i < 8; i++) {
                u64 xp = pack2(xr[i], xr[i]);
                fma2(acc[i][0], xp, w0);
                fma2(acc[i][1], xp, w1);
                fma2(acc[i][2], xp, w2);
                fma2(acc[i][3], xp, w3);
            }
        }
        __syncthreads();
    }

    // epilogue
    __half2* __restrict__ h16o = (BIN == 0 ? g_h16b : g_h16a);
    float colsum[8], colsq[8];
    #pragma unroll
    for (int j = 0; j < 8; j++) { colsum[j] = 0.f; colsq[j] = 0.f; }

    #pragma unroll
    for (int i = 0; i < 8; i++) {
        int row = m0g + mm + i;
        bool ok = row < NN;
        float tval = (!FEAT && ok) ? g_t[row] * g_nd[row] : 0.f;
        #pragma unroll
        for (int jp = 0; jp < 4; jp++) {
            float v0, v1;
            unpack2(acc[i][jp], v0, v1);
            int n0 = nn + jp * 2;
            float va = v0 + sbias[n0];
            float vb = v1 + sbias[n0 + 1];
            if (!FEAT) { va += tval * scvec[n0]; vb += tval * scvec[n0 + 1]; }
            va = fmaxf(va, 0.f); vb = fmaxf(vb, 0.f);
            if (ok) {
                float oa, ob;
                if (!FEAT) {   // residual
                    oa = g_h[row * DD + n0] + va;
                    ob = g_h[row * DD + n0 + 1] + vb;
                } else { oa = va; ob = vb; }
                g_h[row * DD + n0] = oa;
                g_h[row * DD + n0 + 1] = ob;
                if (WH16)
                    h16o[(row * DD + n0) >> 1] = __floats2half2_rn(oa, ob);
                if (STATS) {
                    colsum[jp * 2] += oa;     colsq[jp * 2] += oa * oa;
                    colsum[jp * 2 + 1] += ob; colsq[jp * 2 + 1] += ob * ob;
                }
            }
        }
    }

    if (STATS) {
        float* sred = Ws;            // reuse (mainloop done, synced above)
        float* sqd  = Xst;           // reuse X tile
        #pragma unroll
        for (int j = 0; j < 8; j++) {
            sred[ty * 128 + nn + j] = colsum[j];
            sqd[ty * 128 + nn + j]  = colsq[j];
        }
        __syncthreads();
        if (tid < 128) {
            float s = 0.f, q = 0.f;
            #pragma unroll
            for (int t2 = 0; t2 < 16; t2++) {
                s += sred[t2 * 128 + tid];
                q += sqd[t2 * 128 + tid];
            }
            atomicAdd(&g_sumL[layer + 1][tid], s);
            atomicAdd(&g_sqL[layer + 1][tid], q);
        }
    }
}

// ---------------- pooling + head ----------------
__global__ void pool_kernel(const int* __restrict__ gid) {
    int g = blockIdx.x, c = threadIdx.x;
    int lo = 0, hi = NN;
    while (lo < hi) { int mid = (lo + hi) >> 1; if (gid[mid] < g) lo = mid + 1; else hi = mid; }
    int s0 = lo;
    lo = s0; hi = NN;
    while (lo < hi) { int mid = (lo + hi) >> 1; if (gid[mid] < g + 1) lo = mid + 1; else hi = mid; }
    int s1 = lo;
    float s = 0.f;
    for (int r = s0; r < s1; r++) s += g_h[r * DD + c];
    g_hg[g * DD + c] = s;
    atomicAdd(&g_psum[c], s);
    atomicAdd(&g_psq[c], s * s);
}

__global__ void fc_kernel(const float* __restrict__ W, const float* __restrict__ bias,
                          const float* __restrict__ gma, const float* __restrict__ bta) {
    __shared__ float x[DD];
    int r = blockIdx.x, c = threadIdx.x;
    float m = g_psum[c] * (1.0f / GG);
    float v = g_psq[c] * (1.0f / GG) - m * m;
    float a = gma[c] * rsqrtf(v + EPS);
    float bv = bta[c] - m * a;
    x[c] = g_hg[r * DD + c] * a + bv;
    __syncthreads();
    float s = bias[c];
    #pragma unroll 8
    for (int k = 0; k < DD; k++) s += x[k] * W[k * DD + c];
    float o = fmaxf(s, 0.f);
    g_hg2[r * DD + c] = o;
    atomicAdd(&g_fsum[c], o);
    atomicAdd(&g_fsq[c], o * o);
}

__global__ void cls_kernel(const float* __restrict__ W, const float* __restrict__ bias,
                           const float* __restrict__ gma, const float* __restrict__ bta,
                           float* __restrict__ out) {
    __shared__ float x[DD];
    int r = blockIdx.x, c = threadIdx.x;
    float m = g_fsum[c] * (1.0f / GG);
    float v = g_fsq[c] * (1.0f / GG) - m * m;
    float a = gma[c] * rsqrtf(v + EPS);
    float bv = bta[c] - m * a;
    x[c] = g_hg2[r * DD + c] * a + bv;
    __syncthreads();
    if (c < CC) {
        float s = bias[c];
        for (int k = 0; k < DD; k++) s += x[k] * W[k * CC + c];
        out[r * CC + c] = s;
    }
}

// ---------------- launch ----------------
extern "C" void kernel_launch(void* const* d_in, const int* in_sizes, int n_in,
                              void* d_out, int out_size) {
    const float* h_in      = (const float*)d_in[0];
    const float* bn_feat_g = (const float*)d_in[1];
    const float* bn_feat_b = (const float*)d_in[2];
    const float* feat_W    = (const float*)d_in[3];
    const float* feat_b    = (const float*)d_in[4];
    const float* conv_bn_g = (const float*)d_in[5];
    const float* conv_bn_b = (const float*)d_in[6];
    const float* conv_W    = (const float*)d_in[7];
    const float* conv_b    = (const float*)d_in[8];
    const float* fc_bn_g   = (const float*)d_in[9];
    const float* fc_bn_b   = (const float*)d_in[10];
    const float* fc_W      = (const float*)d_in[11];
    const float* fc_b      = (const float*)d_in[12];
    const float* bn_hid_g  = (const float*)d_in[13];
    const float* bn_hid_b  = (const float*)d_in[14];
    const float* cls_W     = (const float*)d_in[15];
    const float* cls_b     = (const float*)d_in[16];
    const int*   src       = (const int*)d_in[17];
    const int*   dst       = (const int*)d_in[18];
    const int*   gid       = (const int*)d_in[19];
    float* out = (float*)d_out;

    const int nblkN = (NN + 255) / 256;
    const int nblkE = (EE + 255) / 256;
    const int gemmBlks = (NN + 127) / 128;

    static cudaStream_t s2 = nullptr;
    static cudaEvent_t e0, eFill;
    if (s2 == nullptr) {
        cudaStreamCreateWithFlags(&s2, cudaStreamNonBlocking);
        cudaEventCreateWithFlags(&e0, cudaEventDisableTiming);
        cudaEventCreateWithFlags(&eFill, cudaEventDisableTiming);
        cudaFuncSetAttribute(gemm_fused<true, true, true, 1>,
                             cudaFuncAttributeMaxDynamicSharedMemorySize, GEMM_SMEM_B);
        cudaFuncSetAttribute(gemm_fused<false, true, true, 0>,
                             cudaFuncAttributeMaxDynamicSharedMemorySize, GEMM_SMEM_B);
        cudaFuncSetAttribute(gemm_fused<false, true, true, 1>,
                             cudaFuncAttributeMaxDynamicSharedMemorySize, GEMM_SMEM_B);
        cudaFuncSetAttribute(gemm_fused<false, false, false, 0>,
                             cudaFuncAttributeMaxDynamicSharedMemorySize, GEMM_SMEM_B);
    }
    cudaStream_t ms = 0;   // capture (main) stream

    // root
    init_kernel<<<nblkN, 256, 0, ms>>>();
    cudaEventRecord(e0, ms);

    // branch B (side stream): graph structure
    cudaStreamWaitEvent(s2, e0, 0);
    degree_kernel<<<nblkE, 256, 0, s2>>>(src, dst);
    scan1_kernel<<<NSB, 256, 0, s2>>>();
    scan2_kernel<<<1, 128, 0, s2>>>();
    scan3_kernel<<<NSB, 256, 0, s2>>>();
    fill_kernel<<<nblkE, 256, 0, s2>>>(src, dst);
    cudaEventRecord(eFill, s2);

    // branch A (main stream): feat layer (no graph deps)
    stats_in_kernel<<<512, DD, 0, ms>>>(h_in);
    gemm_fused<true, true, true, 1><<<gemmBlks, 256, GEMM_SMEM_B, ms>>>(
        h_in, bn_feat_g, bn_feat_b, feat_W, feat_b, 0);

    // conv layers (fused agg+gemm), need CSR
    cudaStreamWaitEvent(ms, eFill, 0);
    gemm_fused<false, true, true, 0><<<gemmBlks, 256, GEMM_SMEM_B, ms>>>(
        nullptr, conv_bn_g + 0 * DD, conv_bn_b + 0 * DD, conv_W + 0 * DD * DD,
        conv_b + 0 * DD, 1);
    gemm_fused<false, true, true, 1><<<gemmBlks, 256, GEMM_SMEM_B, ms>>>(
        nullptr, conv_bn_g + 1 * DD, conv_bn_b + 1 * DD, conv_W + 1 * DD * DD,
        conv_b + 1 * DD, 2);
    gemm_fused<false, false, false, 0><<<gemmBlks, 256, GEMM_SMEM_B, ms>>>(
        nullptr, conv_bn_g + 2 * DD, conv_bn_b + 2 * DD, conv_W + 2 * DD * DD,
        conv_b + 2 * DD, 3);

    // pooling + head
    pool_kernel<<<GG, DD, 0, ms>>>(gid);
    fc_kernel<<<GG, DD, 0, ms>>>(fc_W, fc_b, fc_bn_g, fc_bn_b);
    cls_kernel<<<GG, DD, 0, ms>>>(cls_W, cls_b, bn_hid_g, bn_hid_b, out);
}

// round 13
// speedup vs baseline: 1.0525x; 1.0462x over previous
#include <cuda_runtime.h>
#include <cuda_fp16.h>
#include <cstdint>

#define NN 100000
#define EE 1600000
#define GG 512
#define DD 128
#define CC 10
#define EPS 1e-5f
#define SB 1024
#define NSB ((NN + SB - 1) / SB)

typedef unsigned long long u64;

// ---------------- device scratch ----------------
__device__ float  g_h[NN * DD];
__device__ __half2 g_h16[NN * (DD / 2)];   // h * ns, fp16, for aggregation gathers
__device__ float  g_X[NN * DD];
__device__ float  g_t[NN];                 // sum of ns over in-edges
__device__ float  g_ns[NN];
__device__ float  g_nd[NN];
__device__ int    g_degO[NN];
__device__ int    g_degI[NN];
__device__ int    g_off[NN + 1];
__device__ int    g_cur[NN];
__device__ int    g_esrc[EE];
__device__ int    g_bsum[128];
__device__ int    g_boff[128];
__device__ float  g_sum[DD], g_sq[DD];
__device__ float  g_Wp[DD * DD], g_cvec[DD], g_bias2[DD];
__device__ float  g_hg[GG * DD], g_hg2[GG * DD];
__device__ float  g_psum[DD], g_psq[DD], g_fsum[DD], g_fsq[DD];

// ---------------- f32x2 helpers ----------------
__device__ __forceinline__ u64 pack2(float lo, float hi) {
    u64 r; asm("mov.b64 %0,{%1,%2};" : "=l"(r) : "f"(lo), "f"(hi)); return r;
}
__device__ __forceinline__ void unpack2(u64 v, float& lo, float& hi) {
    asm("mov.b64 {%0,%1},%2;" : "=f"(lo), "=f"(hi) : "l"(v));
}
__device__ __forceinline__ void fma2(u64& d, u64 a, u64 b) {
    asm("fma.rn.f32x2 %0,%1,%2,%0;" : "+l"(d) : "l"(a), "l"(b));
}

// ---------------- init ----------------
__global__ void init_kernel() {
    int i = blockIdx.x * blockDim.x + threadIdx.x;
    if (i < NN) { g_degO[i] = 0; g_degI[i] = 0; g_t[i] = 0.f; }
    if (i < DD) {
        g_sum[i] = 0.f; g_sq[i] = 0.f;
        g_psum[i] = 0.f; g_psq[i] = 0.f;
        g_fsum[i] = 0.f; g_fsq[i] = 0.f;
    }
}

__global__ void degree_kernel(const int* __restrict__ src, const int* __restrict__ dst) {
    int e = blockIdx.x * blockDim.x + threadIdx.x;
    if (e < EE) {
        atomicAdd(&g_degO[src[e]], 1);
        atomicAdd(&g_degI[dst[e]], 1);
    }
}

// ---------------- 3-pass scan over g_degI ----------------
__global__ void scan1_kernel() {
    __shared__ int wsum[8];
    int b = blockIdx.x, tid = threadIdx.x;
    int base = b * SB + tid * 4;
    int s = 0;
    #pragma unroll
    for (int u = 0; u < 4; u++) { int i = base + u; if (i < NN) s += g_degI[i]; }
    int lane = tid & 31, wid = tid >> 5;
    #pragma unroll
    for (int o = 16; o > 0; o >>= 1) s += __shfl_down_sync(0xffffffffu, s, o);
    if (lane == 0) wsum[wid] = s;
    __syncthreads();
    if (tid == 0) {
        int t = 0;
        #pragma unroll
        for (int w = 0; w < 8; w++) t += wsum[w];
        g_bsum[b] = t;
    }
}

__global__ void scan2_kernel() {
    __shared__ int ws[4];
    int tid = threadIdx.x;
    int lane = tid & 31, wid = tid >> 5;
    int v = (tid < NSB) ? g_bsum[tid] : 0;
    int x = v;
    #pragma unroll
    for (int o = 1; o < 32; o <<= 1) {
        int y = __shfl_up_sync(0xffffffffu, x, o);
        if (lane >= o) x += y;
    }
    if (lane == 31) ws[wid] = x;
    __syncthreads();
    if (tid == 0) {
        int c = 0;
        #pragma unroll
        for (int w = 0; w < 4; w++) { int t = ws[w]; ws[w] = c; c += t; }
    }
    __syncthreads();
    int excl = x - v + ws[wid];
    if (tid < NSB) g_boff[tid] = excl;
    if (tid == 0) g_off[NN] = EE;
}

__global__ void scan3_kernel() {
    __shared__ int wsum[8];
    int b = blockIdx.x, tid = threadIdx.x;
    int base = b * SB + tid * 4;
    int v[4];
    #pragma unroll
    for (int u = 0; u < 4; u++) {
        int i = base + u;
        v[u] = (i < NN) ? g_degI[i] : 0;
    }
    int tot = v[0] + v[1] + v[2] + v[3];
    int lane = tid & 31, wid = tid >> 5;
    int x = tot;
    #pragma unroll
    for (int o = 1; o < 32; o <<= 1) {
        int y = __shfl_up_sync(0xffffffffu, x, o);
        if (lane >= o) x += y;
    }
    if (lane == 31) wsum[wid] = x;
    __syncthreads();
    if (wid == 0 && lane < 8) {
        int w = wsum[lane];
        int xx = w;
        #pragma unroll
        for (int o = 1; o < 8; o <<= 1) {
            int y = __shfl_up_sync(0xffu, xx, o);
            if (lane >= o) xx += y;
        }
        wsum[lane] = xx - w;
    }
    __syncthreads();
    int p = x - tot + wsum[wid] + g_boff[b];
    #pragma unroll
    for (int u = 0; u < 4; u++) {
        int i = base + u;
        if (i < NN) {
            g_off[i] = p; g_cur[i] = p; p += v[u];
            g_nd[i] = rsqrtf((float)max(v[u], 1));
            g_ns[i] = rsqrtf((float)max(g_degO[i], 1));
        }
    }
}

// fill CSR + accumulate sum of ns[src] per dst
__global__ void fill_kernel(const int* __restrict__ src, const int* __restrict__ dst) {
    int e = blockIdx.x * blockDim.x + threadIdx.x;
    if (e < EE) {
        int s = src[e], d = dst[e];
        int p = atomicAdd(&g_cur[d], 1);
        g_esrc[p] = s;
        atomicAdd(&g_t[d], g_ns[s]);
    }
}

// ---------------- BN stats over external input (feat layer only) ----------------
__global__ void stats_in_kernel(const float* __restrict__ x) {
    int c = threadIdx.x;
    float s = 0.f, q = 0.f;
    for (int r = blockIdx.x; r < NN; r += gridDim.x) {
        float v = x[r * DD + c];
        s += v; q += v * v;
    }
    atomicAdd(&g_sum[c], s);
    atomicAdd(&g_sq[c], q);
}

// ---------------- finprep ----------------
__global__ void finprep_kernel(const float* __restrict__ g, const float* __restrict__ b,
                               const float* __restrict__ W, const float* __restrict__ addb,
                               int mode) {
    __shared__ float sa[DD], sbv[DD];
    __shared__ float red[8][DD];
    int tid = threadIdx.x;
    if (tid < DD) {
        float m = g_sum[tid] * (1.0f / NN);
        float v = g_sq[tid] * (1.0f / NN) - m * m;
        float a = g[tid] * rsqrtf(v + EPS);
        sa[tid] = a;
        sbv[tid] = b[tid] - m * a;
    }
    __syncthreads();
    for (int i = tid; i < DD * DD; i += 1024)
        g_Wp[i] = sa[i >> 7] * W[i];
    int n = tid & 127, part = tid >> 7;
    float s = 0.f;
    for (int k = part * 16; k < part * 16 + 16; k++)
        s += sbv[k] * W[k * DD + n];
    red[part][n] = s;
    __syncthreads();
    if (tid < DD) {
        float t = 0.f;
        #pragma unroll
        for (int p = 0; p < 8; p++) t += red[p][n];
        if (mode == 0) g_bias2[n] = addb[n] + t;
        else         { g_cvec[n] = t; g_bias2[n] = addb[n]; }
        g_sum[n] = 0.f; g_sq[n] = 0.f;
    }
}

// ---------------- edge aggregation (fp16 gathers, 4-way MLP batching) ----------------
__global__ void agg_kernel() {
    int warp = (blockIdx.x * blockDim.x + threadIdx.x) >> 5;
    int lane = threadIdx.x & 31;
    if (warp >= NN) return;
    int beg = g_off[warp], end = g_off[warp + 1];
    float a0 = 0.f, a1 = 0.f, a2 = 0.f, a3 = 0.f;
    const uint2* __restrict__ h2 = (const uint2*)g_h16;
    int e = beg;
    for (; e + 4 <= end; e += 4) {
        int s0 = g_esrc[e], s1 = g_esrc[e + 1], s2 = g_esrc[e + 2], s3 = g_esrc[e + 3];
        uint2 v0 = h2[(size_t)s0 * 32 + lane];
        uint2 v1 = h2[(size_t)s1 * 32 + lane];
        uint2 v2 = h2[(size_t)s2 * 32 + lane];
        uint2 v3 = h2[(size_t)s3 * 32 + lane];
        float2 f;
        f = __half22float2(*(__half2*)&v0.x); a0 += f.x; a1 += f.y;
        f = __half22float2(*(__half2*)&v0.y); a2 += f.x; a3 += f.y;
        f = __half22float2(*(__half2*)&v1.x); a0 += f.x; a1 += f.y;
        f = __half22float2(*(__half2*)&v1.y); a2 += f.x; a3 += f.y;
        f = __half22float2(*(__half2*)&v2.x); a0 += f.x; a1 += f.y;
        f = __half22float2(*(__half2*)&v2.y); a2 += f.x; a3 += f.y;
        f = __half22float2(*(__half2*)&v3.x); a0 += f.x; a1 += f.y;
        f = __half22float2(*(__half2*)&v3.y); a2 += f.x; a3 += f.y;
    }
    for (; e < end; e++) {
        int s = g_esrc[e];
        uint2 hv = h2[(size_t)s * 32 + lane];
        float2 f0 = __half22float2(*(__half2*)&hv.x);
        float2 f1 = __half22float2(*(__half2*)&hv.y);
        a0 += f0.x; a1 += f0.y; a2 += f1.x; a3 += f1.y;
    }
    float nd = g_nd[warp];
    ((float4*)g_X)[warp * 32 + lane] = make_float4(a0 * nd, a1 * nd, a2 * nd, a3 * nd);
}

// ---------------- main GEMM (f32x2, R4-proven mainloop) ----------------
template <bool RESID, bool HAST, bool XG, bool STATS, bool WH16>
__global__ void __launch_bounds__(256, 2)
gemm_kernel(const float* __restrict__ Xext, int nrows) {
    __shared__ float Xs[32][129];   // transposed, pad 1 -> conflict-free
    __shared__ float Ws[32][128];
    const float* __restrict__ X = XG ? g_X : Xext;
    int tid = threadIdx.x;
    int m0g = blockIdx.x * 128;
    int tx = tid & 15, ty = tid >> 4;
    int mm = ty * 8, nn = tx * 8;
    u64 acc[8][4];
    #pragma unroll
    for (int i = 0; i < 8; i++)
        #pragma unroll
        for (int j = 0; j < 4; j++) acc[i][j] = pack2(0.f, 0.f);

    for (int kc = 0; kc < 4; kc++) {
        int k0 = kc * 32;
        #pragma unroll
        for (int it = 0; it < 4; it++) {
            int idx = tid + it * 256;
            int row = idx >> 3, kq = idx & 7;
            int gr = m0g + row;
            float4 v = make_float4(0.f, 0.f, 0.f, 0.f);
            if (gr < nrows) v = *(const float4*)(X + gr * DD + k0 + kq * 4);
            Xs[kq * 4 + 0][row] = v.x;
            Xs[kq * 4 + 1][row] = v.y;
            Xs[kq * 4 + 2][row] = v.z;
            Xs[kq * 4 + 3][row] = v.w;
        }
        #pragma unroll
        for (int it = 0; it < 4; it++) {
            int idx = tid + it * 256;
            int kr = idx >> 5, nq = idx & 31;
            *(float4*)&Ws[kr][nq * 4] = *(const float4*)(g_Wp + (k0 + kr) * DD + nq * 4);
        }
        __syncthreads();
        #pragma unroll
        for (int k = 0; k < 32; k++) {
            float xr[8];
            #pragma unroll
            for (int i = 0; i < 8; i++) xr[i] = Xs[k][mm + i];
            ulonglong2 wa = *(const ulonglong2*)&Ws[k][nn];
            ulonglong2 wb = *(const ulonglong2*)&Ws[k][nn + 4];
            u64 w0 = wa.x, w1 = wa.y, w2 = wb.x, w3 = wb.y;
            #pragma unroll
            for (int i = 0; i < 8; i++) {
                u64 xp = pack2(xr[i], xr[i]);
                fma2(acc[i][0], xp, w0);
                fma2(acc[i][1], xp, w1);
                fma2(acc[i][2], xp, w2);
                fma2(acc[i][3], xp, w3);
            }
        }
        __syncthreads();
    }

    // epilogue
    float colsum[8], colsq[8];
    #pragma unroll
    for (int j = 0; j < 8; j++) { colsum[j] = 0.f; colsq[j] = 0.f; }

    #pragma unroll
    for (int i = 0; i < 8; i++) {
        int row = m0g + mm + i;
        bool ok = row < nrows;
        float tval = (HAST && ok) ? g_t[row] * g_nd[row] : 0.f;
        float nsv = (WH16 && ok) ? g_ns[row] : 0.f;
        #pragma unroll
        for (int jp = 0; jp < 4; jp++) {
            float v0, v1;
            unpack2(acc[i][jp], v0, v1);
            int n0 = nn + jp * 2;
            float va = v0 + g_bias2[n0];
            float vb = v1 + g_bias2[n0 + 1];
            if (HAST) { va += tval * g_cvec[n0]; vb += tval * g_cvec[n0 + 1]; }
            va = fmaxf(va, 0.f); vb = fmaxf(vb, 0.f);
            if (ok) {
                float oa, ob;
                if (RESID) {
                    oa = g_h[row * DD + n0] + va;
                    ob = g_h[row * DD + n0 + 1] + vb;
                } else { oa = va; ob = vb; }
                g_h[row * DD + n0] = oa;
                g_h[row * DD + n0 + 1] = ob;
                if (WH16)
                    g_h16[(row * DD + n0) >> 1] = __floats2half2_rn(oa * nsv, ob * nsv);
                if (STATS) {
                    colsum[jp * 2] += oa;     colsq[jp * 2] += oa * oa;
                    colsum[jp * 2 + 1] += ob; colsq[jp * 2 + 1] += ob * ob;
                }
            }
        }
    }

    if (STATS) {
        float* sred = (float*)Xs;
        float* sqd  = (float*)Ws;
        #pragma unroll
        for (int j = 0; j < 8; j++) {
            sred[ty * 128 + nn + j] = colsum[j];
            sqd[ty * 128 + nn + j]  = colsq[j];
        }
        __syncthreads();
        if (tid < 128) {
            float s = 0.f, q = 0.f;
            #pragma unroll
            for (int t2 = 0; t2 < 16; t2++) {
                s += sred[t2 * 128 + tid];
                q += sqd[t2 * 128 + tid];
            }
            atomicAdd(&g_sum[tid], s);
            atomicAdd(&g_sq[tid], q);
        }
    }
}

// ---------------- pooling + head ----------------
__global__ void pool_kernel(const int* __restrict__ gid) {
    int g = blockIdx.x, c = threadIdx.x;
    int lo = 0, hi = NN;
    while (lo < hi) { int mid = (lo + hi) >> 1; if (gid[mid] < g) lo = mid + 1; else hi = mid; }
    int s0 = lo;
    lo = s0; hi = NN;
    while (lo < hi) { int mid = (lo + hi) >> 1; if (gid[mid] < g + 1) lo = mid + 1; else hi = mid; }
    int s1 = lo;
    float s = 0.f;
    for (int r = s0; r < s1; r++) s += g_h[r * DD + c];
    g_hg[g * DD + c] = s;
    atomicAdd(&g_psum[c], s);
    atomicAdd(&g_psq[c], s * s);
}

__global__ void fc_kernel(const float* __restrict__ W, const float* __restrict__ bias,
                          const float* __restrict__ gma, const float* __restrict__ bta) {
    __shared__ float x[DD];
    int r = blockIdx.x, c = threadIdx.x;
    float m = g_psum[c] * (1.0f / GG);
    float v = g_psq[c] * (1.0f / GG) - m * m;
    float a = gma[c] * rsqrtf(v + EPS);
    float bv = bta[c] - m * a;
    x[c] = g_hg[r * DD + c] * a + bv;
    __syncthreads();
    float s = bias[c];
    #pragma unroll 8
    for (int k = 0; k < DD; k++) s += x[k] * W[k * DD + c];
    float o = fmaxf(s, 0.f);
    g_hg2[r * DD + c] = o;
    atomicAdd(&g_fsum[c], o);
    atomicAdd(&g_fsq[c], o * o);
}

__global__ void cls_kernel(const float* __restrict__ W, const float* __restrict__ bias,
                           const float* __restrict__ gma, const float* __restrict__ bta,
                           float* __restrict__ out) {
    __shared__ float x[DD];
    int r = blockIdx.x, c = threadIdx.x;
    float m = g_fsum[c] * (1.0f / GG);
    float v = g_fsq[c] * (1.0f / GG) - m * m;
    float a = gma[c] * rsqrtf(v + EPS);
    float bv = bta[c] - m * a;
    x[c] = g_hg2[r * DD + c] * a + bv;
    __syncthreads();
    if (c < CC) {
        float s = bias[c];
        for (int k = 0; k < DD; k++) s += x[k] * W[k * CC + c];
        out[r * CC + c] = s;
    }
}

// ---------------- launch (forked graph: preprocess ∥ feat layer) ----------------
extern "C" void kernel_launch(void* const* d_in, const int* in_sizes, int n_in,
                              void* d_out, int out_size) {
    const float* h_in      = (const float*)d_in[0];
    const float* bn_feat_g = (const float*)d_in[1];
    const float* bn_feat_b = (const float*)d_in[2];
    const float* feat_W    = (const float*)d_in[3];
    const float* feat_b    = (const float*)d_in[4];
    const float* conv_bn_g = (const float*)d_in[5];
    const float* conv_bn_b = (const float*)d_in[6];
    const float* conv_W    = (const float*)d_in[7];
    const float* conv_b    = (const float*)d_in[8];
    const float* fc_bn_g   = (const float*)d_in[9];
    const float* fc_bn_b   = (const float*)d_in[10];
    const float* fc_W      = (const float*)d_in[11];
    const float* fc_b      = (const float*)d_in[12];
    const float* bn_hid_g  = (const float*)d_in[13];
    const float* bn_hid_b  = (const float*)d_in[14];
    const float* cls_W     = (const float*)d_in[15];
    const float* cls_b     = (const float*)d_in[16];
    const int*   src       = (const int*)d_in[17];
    const int*   dst       = (const int*)d_in[18];
    const int*   gid       = (const int*)d_in[19];
    float* out = (float*)d_out;

    const int nblkN = (NN + 255) / 256;
    const int nblkE = (EE + 255) / 256;
    const int gemmBlks = (NN + 127) / 128;
    const int aggBlks = (NN * 32 + 255) / 256;

    static cudaStream_t s2 = nullptr;
    static cudaEvent_t e0, eFill, eG[3], eP[3];
    if (s2 == nullptr) {
        cudaStreamCreateWithFlags(&s2, cudaStreamNonBlocking);
        cudaEventCreateWithFlags(&e0, cudaEventDisableTiming);
        cudaEventCreateWithFlags(&eFill, cudaEventDisableTiming);
        for (int i = 0; i < 3; i++) {
            cudaEventCreateWithFlags(&eG[i], cudaEventDisableTiming);
            cudaEventCreateWithFlags(&eP[i], cudaEventDisableTiming);
        }
    }
    cudaStream_t ms = 0;   // capture (main) stream

    // root
    init_kernel<<<nblkN, 256, 0, ms>>>();
    cudaEventRecord(e0, ms);

    // branch B (side stream): graph structure
    cudaStreamWaitEvent(s2, e0, 0);
    degree_kernel<<<nblkE, 256, 0, s2>>>(src, dst);
    scan1_kernel<<<NSB, 256, 0, s2>>>();
    scan2_kernel<<<1, 128, 0, s2>>>();
    scan3_kernel<<<NSB, 256, 0, s2>>>();
    fill_kernel<<<nblkE, 256, 0, s2>>>(src, dst);
    cudaEventRecord(eFill, s2);

    // branch A (main stream): feat layer
    stats_in_kernel<<<512, DD, 0, ms>>>(h_in);
    finprep_kernel<<<1, 1024, 0, ms>>>(bn_feat_g, bn_feat_b, feat_W, feat_b, 0);
    gemm_kernel<false, false, false, true, true><<<gemmBlks, 256, 0, ms>>>(h_in, NN);

    // conv layers: finprep_i on side stream overlaps agg_i on main
    const float* cW[3] = {conv_W, conv_W + DD * DD, conv_W + 2 * DD * DD};
    cudaEventRecord(eG[0], ms);
    cudaStreamWaitEvent(ms, eFill, 0);   // agg needs CSR
    for (int i = 0; i < 3; i++) {
        cudaStreamWaitEvent(s2, eG[i], 0);
        finprep_kernel<<<1, 1024, 0, s2>>>(conv_bn_g + i * DD, conv_bn_b + i * DD,
                                           cW[i], conv_b + i * DD, 1);
        cudaEventRecord(eP[i], s2);

        agg_kernel<<<aggBlks, 256, 0, ms>>>();
        cudaStreamWaitEvent(ms, eP[i], 0);
        if (i < 2) {
            gemm_kernel<true, true, true, true, true><<<gemmBlks, 256, 0, ms>>>(nullptr, NN);
            cudaEventRecord(eG[i + 1], ms);
        } else {
            gemm_kernel<true, true, true, false, false><<<gemmBlks, 256, 0, ms>>>(nullptr, NN);
        }
    }

    // pooling + head
    pool_kernel<<<GG, DD, 0, ms>>>(gid);
    fc_kernel<<<GG, DD, 0, ms>>>(fc_W, fc_b, fc_bn_g, fc_bn_b);
    cls_kernel<<<GG, DD, 0, ms>>>(cls_W, cls_b, bn_hid_g, bn_hid_b, out);
}

// round 14
// speedup vs baseline: 1.3295x; 1.2632x over previous
#include <cuda_runtime.h>
#include <cuda_fp16.h>
#include <cstdint>

#define NN 100000
#define EE 1600000
#define GG 512
#define DD 128
#define CC 10
#define EPS 1e-5f
#define SB 1024
#define NSB ((NN + SB - 1) / SB)

typedef unsigned long long u64;

// ---------------- device scratch ----------------
__device__ float  g_h[NN * DD];
__device__ __half2 g_h16[NN * (DD / 2)];   // h * ns, fp16, for aggregation gathers
__device__ float  g_X[NN * DD];
__device__ float  g_t[NN];
__device__ float  g_ns[NN];
__device__ float  g_nd[NN];
__device__ int    g_degO[NN];
__device__ int    g_degI[NN];
__device__ int    g_off[NN + 1];
__device__ int    g_cur[NN];
__device__ int    g_esrc[EE];
__device__ int    g_bsum[128];
__device__ int    g_boff[128];
__device__ float  g_sum[DD], g_sq[DD];
__device__ __half g_Whi[DD * DD], g_Wlo[DD * DD];   // BN-folded W, fp16 hi/lo, [k][n]
__device__ float  g_cvec[DD], g_bias2[DD];
__device__ float  g_hg[GG * DD], g_hg2[GG * DD];
__device__ float  g_psum[DD], g_psq[DD], g_fsum[DD], g_fsq[DD];

static __device__ __forceinline__ uint32_t smem_u32(const void* p) {
    uint32_t a;
    asm("{ .reg .u64 t; cvta.to.shared.u64 t, %1; cvt.u32.u64 %0, t; }" : "=r"(a) : "l"(p));
    return a;
}

#define LDSM_X4(r0, r1, r2, r3, addr) \
    asm volatile("ldmatrix.sync.aligned.m8n8.x4.shared.b16 {%0,%1,%2,%3},[%4];" \
        : "=r"(r0), "=r"(r1), "=r"(r2), "=r"(r3) : "r"(addr))

#define LDSM_X4_T(r0, r1, r2, r3, addr) \
    asm volatile("ldmatrix.sync.aligned.m8n8.x4.trans.shared.b16 {%0,%1,%2,%3},[%4];" \
        : "=r"(r0), "=r"(r1), "=r"(r2), "=r"(r3) : "r"(addr))

#define MMA16816(c, a0, a1, a2, a3, b0, b1) \
    asm volatile("mma.sync.aligned.m16n8k16.row.col.f32.f16.f16.f32 " \
        "{%0,%1,%2,%3},{%4,%5,%6,%7},{%8,%9},{%0,%1,%2,%3};" \
        : "+f"((c)[0]), "+f"((c)[1]), "+f"((c)[2]), "+f"((c)[3]) \
        : "r"(a0), "r"(a1), "r"(a2), "r"(a3), "r"(b0), "r"(b1))

// ---------------- init ----------------
__global__ void init_kernel() {
    int i = blockIdx.x * blockDim.x + threadIdx.x;
    if (i < NN) { g_degO[i] = 0; g_degI[i] = 0; g_t[i] = 0.f; }
    if (i < DD) {
        g_sum[i] = 0.f; g_sq[i] = 0.f;
        g_psum[i] = 0.f; g_psq[i] = 0.f;
        g_fsum[i] = 0.f; g_fsq[i] = 0.f;
    }
}

__global__ void degree_kernel(const int* __restrict__ src, const int* __restrict__ dst) {
    int e = blockIdx.x * blockDim.x + threadIdx.x;
    if (e < EE) {
        atomicAdd(&g_degO[src[e]], 1);
        atomicAdd(&g_degI[dst[e]], 1);
    }
}

// ---------------- 3-pass scan ----------------
__global__ void scan1_kernel() {
    __shared__ int wsum[8];
    int b = blockIdx.x, tid = threadIdx.x;
    int base = b * SB + tid * 4;
    int s = 0;
    #pragma unroll
    for (int u = 0; u < 4; u++) { int i = base + u; if (i < NN) s += g_degI[i]; }
    int lane = tid & 31, wid = tid >> 5;
    #pragma unroll
    for (int o = 16; o > 0; o >>= 1) s += __shfl_down_sync(0xffffffffu, s, o);
    if (lane == 0) wsum[wid] = s;
    __syncthreads();
    if (tid == 0) {
        int t = 0;
        #pragma unroll
        for (int w = 0; w < 8; w++) t += wsum[w];
        g_bsum[b] = t;
    }
}

__global__ void scan2_kernel() {
    __shared__ int ws[4];
    int tid = threadIdx.x;
    int lane = tid & 31, wid = tid >> 5;
    int v = (tid < NSB) ? g_bsum[tid] : 0;
    int x = v;
    #pragma unroll
    for (int o = 1; o < 32; o <<= 1) {
        int y = __shfl_up_sync(0xffffffffu, x, o);
        if (lane >= o) x += y;
    }
    if (lane == 31) ws[wid] = x;
    __syncthreads();
    if (tid == 0) {
        int c = 0;
        #pragma unroll
        for (int w = 0; w < 4; w++) { int t = ws[w]; ws[w] = c; c += t; }
    }
    __syncthreads();
    int excl = x - v + ws[wid];
    if (tid < NSB) g_boff[tid] = excl;
    if (tid == 0) g_off[NN] = EE;
}

__global__ void scan3_kernel() {
    __shared__ int wsum[8];
    int b = blockIdx.x, tid = threadIdx.x;
    int base = b * SB + tid * 4;
    int v[4];
    #pragma unroll
    for (int u = 0; u < 4; u++) {
        int i = base + u;
        v[u] = (i < NN) ? g_degI[i] : 0;
    }
    int tot = v[0] + v[1] + v[2] + v[3];
    int lane = tid & 31, wid = tid >> 5;
    int x = tot;
    #pragma unroll
    for (int o = 1; o < 32; o <<= 1) {
        int y = __shfl_up_sync(0xffffffffu, x, o);
        if (lane >= o) x += y;
    }
    if (lane == 31) wsum[wid] = x;
    __syncthreads();
    if (wid == 0 && lane < 8) {
        int w = wsum[lane];
        int xx = w;
        #pragma unroll
        for (int o = 1; o < 8; o <<= 1) {
            int y = __shfl_up_sync(0xffu, xx, o);
            if (lane >= o) xx += y;
        }
        wsum[lane] = xx - w;
    }
    __syncthreads();
    int p = x - tot + wsum[wid] + g_boff[b];
    #pragma unroll
    for (int u = 0; u < 4; u++) {
        int i = base + u;
        if (i < NN) {
            g_off[i] = p; g_cur[i] = p; p += v[u];
            g_nd[i] = rsqrtf((float)max(v[u], 1));
            g_ns[i] = rsqrtf((float)max(g_degO[i], 1));
        }
    }
}

__global__ void fill_kernel(const int* __restrict__ src, const int* __restrict__ dst) {
    int e = blockIdx.x * blockDim.x + threadIdx.x;
    if (e < EE) {
        int s = src[e], d = dst[e];
        int p = atomicAdd(&g_cur[d], 1);
        g_esrc[p] = s;
        atomicAdd(&g_t[d], g_ns[s]);
    }
}

// ---------------- BN stats over external input ----------------
__global__ void stats_in_kernel(const float* __restrict__ x) {
    int c = threadIdx.x;
    float s = 0.f, q = 0.f;
    for (int r = blockIdx.x; r < NN; r += gridDim.x) {
        float v = x[r * DD + c];
        s += v; q += v * v;
    }
    atomicAdd(&g_sum[c], s);
    atomicAdd(&g_sq[c], q);
}

// ---------------- finprep: BN fold -> fp16 hi/lo W split ----------------
__global__ void finprep_kernel(const float* __restrict__ g, const float* __restrict__ b,
                               const float* __restrict__ W, const float* __restrict__ addb,
                               int mode) {
    __shared__ float sa[DD], sbv[DD];
    __shared__ float red[8][DD];
    int tid = threadIdx.x;
    if (tid < DD) {
        float m = g_sum[tid] * (1.0f / NN);
        float v = g_sq[tid] * (1.0f / NN) - m * m;
        float a = g[tid] * rsqrtf(v + EPS);
        sa[tid] = a;
        sbv[tid] = b[tid] - m * a;
    }
    __syncthreads();
    for (int i = tid; i < DD * DD; i += 1024) {
        float wp = sa[i >> 7] * W[i];
        __half hi = __float2half(wp);
        g_Whi[i] = hi;
        g_Wlo[i] = __float2half(wp - __half2float(hi));
    }
    int n = tid & 127, part = tid >> 7;
    float s = 0.f;
    for (int k = part * 16; k < part * 16 + 16; k++)
        s += sbv[k] * W[k * DD + n];
    red[part][n] = s;
    __syncthreads();
    if (tid < DD) {
        float t = 0.f;
        #pragma unroll
        for (int p = 0; p < 8; p++) t += red[p][n];
        if (mode == 0) g_bias2[n] = addb[n] + t;
        else         { g_cvec[n] = t; g_bias2[n] = addb[n]; }
        g_sum[n] = 0.f; g_sq[n] = 0.f;
    }
}

// ---------------- edge aggregation (R9-proven loop) ----------------
__global__ void agg_kernel() {
    int warp = (blockIdx.x * blockDim.x + threadIdx.x) >> 5;
    int lane = threadIdx.x & 31;
    if (warp >= NN) return;
    int beg = g_off[warp], end = g_off[warp + 1];
    float a0 = 0.f, a1 = 0.f, a2 = 0.f, a3 = 0.f;
    const uint2* __restrict__ h2 = (const uint2*)g_h16;
    for (int e = beg; e < end; e++) {
        int s = g_esrc[e];
        uint2 hv = h2[(size_t)s * 32 + lane];
        float2 f0 = __half22float2(*(__half2*)&hv.x);
        float2 f1 = __half22float2(*(__half2*)&hv.y);
        a0 += f0.x; a1 += f0.y; a2 += f1.x; a3 += f1.y;
    }
    float nd = g_nd[warp];
    ((float4*)g_X)[warp * 32 + lane] = make_float4(a0 * nd, a1 * nd, a2 * nd, a3 * nd);
}

// ---------------- HMMA GEMM: D = Xhi@Whi + Xlo@Whi + Xhi@Wlo ----------------
// smem halves: AH [128][136] @0, AL @17408, WS [16][136] @34816 (36992 halves)
// smem floats @73984B: sbias[128], scvec[128], scol[128], ssq[128]
#define AH_OFF 0
#define AL_OFF 17408
#define WS_OFF 34816
#define GSM_BYTES (73984 + 2048)

template <bool RESID, bool HAST, bool FEAT, bool STATS, bool WH16>
__global__ void __launch_bounds__(256, 2)
gemm_mma(const float* __restrict__ Xext) {
    extern __shared__ __align__(16) char smraw[];
    __half* smh = (__half*)smraw;
    float* smf = (float*)(smraw + 73984);
    float* sbias = smf;
    float* scvec = smf + 128;
    float* scol  = smf + 256;
    float* ssq   = smf + 384;

    int tid = threadIdx.x;
    int m0g = blockIdx.x * 128;
    int wid = tid >> 5, l = tid & 31;
    int wm = wid >> 1, wn = wid & 1;
    int gid4 = l >> 2, tig = l & 3;
    uint32_t smb = smem_u32(smraw);

    if (tid < 128) {
        sbias[tid] = g_bias2[tid];
        scvec[tid] = HAST ? g_cvec[tid] : 0.f;
        if (STATS) { scol[tid] = 0.f; ssq[tid] = 0.f; }
    }

    // stage X hi/lo
    const float* __restrict__ Xsrc = FEAT ? Xext : g_X;
    #pragma unroll
    for (int it = 0; it < 16; it++) {
        int idx = tid + it * 256;
        int row = idx >> 5, k4 = idx & 31;
        int gr = m0g + row;
        float4 v = make_float4(0.f, 0.f, 0.f, 0.f);
        if (gr < NN) v = ((const float4*)Xsrc)[gr * 32 + k4];
        __half h0 = __float2half(v.x), h1 = __float2half(v.y);
        __half h2v = __float2half(v.z), h3 = __float2half(v.w);
        __half lo0 = __float2half(v.x - __half2float(h0));
        __half lo1 = __float2half(v.y - __half2float(h1));
        __half lo2 = __float2half(v.z - __half2float(h2v));
        __half lo3 = __float2half(v.w - __half2float(h3));
        __half2* ph = (__half2*)&smh[AH_OFF + row * 136 + k4 * 4];
        ph[0] = __halves2half2(h0, h1);
        ph[1] = __halves2half2(h2v, h3);
        __half2* pl = (__half2*)&smh[AL_OFF + row * 136 + k4 * 4];
        pl[0] = __halves2half2(lo0, lo1);
        pl[1] = __halves2half2(lo2, lo3);
    }
    __syncthreads();

    float acc[2][8][4];
    #pragma unroll
    for (int tm = 0; tm < 2; tm++)
        #pragma unroll
        for (int tn = 0; tn < 8; tn++)
            #pragma unroll
            for (int j = 0; j < 4; j++) acc[tm][tn][j] = 0.f;

    // per-lane address components (half-index)
    int aoff0 = (wm * 32 + 0 * 16 + (l & 15)) * 136 + ((l >> 4) << 3);
    int aoff1 = (wm * 32 + 1 * 16 + (l & 15)) * 136 + ((l >> 4) << 3);
    int boff  = WS_OFF + (l & 15) * 136 + wn * 64 + ((l >> 4) << 3);
    int wr = tid >> 4, wg = tid & 15;   // W staging thread roles

    // pass 1: Whi chunks; A = hi then lo
    for (int c = 0; c < 8; c++) {
        __syncthreads();
        *(uint4*)&smh[WS_OFF + wr * 136 + wg * 8] =
            *(const uint4*)(g_Whi + (c * 16 + wr) * 128 + wg * 8);
        __syncthreads();
        int kk = c * 16;
        uint32_t b[4][4];
        #pragma unroll
        for (int bt = 0; bt < 4; bt++)
            LDSM_X4_T(b[bt][0], b[bt][1], b[bt][2], b[bt][3],
                      smb + 2 * (boff + bt * 16));
        #pragma unroll
        for (int tm = 0; tm < 2; tm++) {
            uint32_t a0, a1, a2, a3;
            LDSM_X4(a0, a1, a2, a3,
                    smb + 2 * (AH_OFF + (tm ? aoff1 : aoff0) + kk));
            #pragma unroll
            for (int tn = 0; tn < 8; tn++) {
                int bt = tn >> 1, hi2 = (tn & 1) * 2;
                MMA16816(acc[tm][tn], a0, a1, a2, a3, b[bt][hi2], b[bt][hi2 + 1]);
            }
        }
        #pragma unroll
        for (int tm = 0; tm < 2; tm++) {
            uint32_t a0, a1, a2, a3;
            LDSM_X4(a0, a1, a2, a3,
                    smb + 2 * (AL_OFF + (tm ? aoff1 : aoff0) + kk));
            #pragma unroll
            for (int tn = 0; tn < 8; tn++) {
                int bt = tn >> 1, hi2 = (tn & 1) * 2;
                MMA16816(acc[tm][tn], a0, a1, a2, a3, b[bt][hi2], b[bt][hi2 + 1]);
            }
        }
    }
    // pass 2: Wlo chunks; A = hi
    for (int c = 0; c < 8; c++) {
        __syncthreads();
        *(uint4*)&smh[WS_OFF + wr * 136 + wg * 8] =
            *(const uint4*)(g_Wlo + (c * 16 + wr) * 128 + wg * 8);
        __syncthreads();
        int kk = c * 16;
        uint32_t b[4][4];
        #pragma unroll
        for (int bt = 0; bt < 4; bt++)
            LDSM_X4_T(b[bt][0], b[bt][1], b[bt][2], b[bt][3],
                      smb + 2 * (boff + bt * 16));
        #pragma unroll
        for (int tm = 0; tm < 2; tm++) {
            uint32_t a0, a1, a2, a3;
            LDSM_X4(a0, a1, a2, a3,
                    smb + 2 * (AH_OFF + (tm ? aoff1 : aoff0) + kk));
            #pragma unroll
            for (int tn = 0; tn < 8; tn++) {
                int bt = tn >> 1, hi2 = (tn & 1) * 2;
                MMA16816(acc[tm][tn], a0, a1, a2, a3, b[bt][hi2], b[bt][hi2 + 1]);
            }
        }
    }

    // epilogue
    float colsum[16], colsq[16];
    if (STATS) {
        #pragma unroll
        for (int j = 0; j < 16; j++) { colsum[j] = 0.f; colsq[j] = 0.f; }
    }
    #pragma unroll
    for (int tm = 0; tm < 2; tm++) {
        #pragma unroll
        for (int hf = 0; hf < 2; hf++) {
            int row = m0g + wm * 32 + tm * 16 + gid4 + hf * 8;
            if (row >= NN) continue;
            float tval = HAST ? g_t[row] * g_nd[row] : 0.f;
            float nsv = WH16 ? g_ns[row] : 0.f;
            #pragma unroll
            for (int tn = 0; tn < 8; tn++) {
                int cc = wn * 64 + tn * 8 + tig * 2;
                float va = acc[tm][tn][hf * 2 + 0] + sbias[cc];
                float vb = acc[tm][tn][hf * 2 + 1] + sbias[cc + 1];
                if (HAST) { va += tval * scvec[cc]; vb += tval * scvec[cc + 1]; }
                va = fmaxf(va, 0.f); vb = fmaxf(vb, 0.f);
                float oa, ob;
                if (RESID) {
                    float2 old = *(float2*)(g_h + row * DD + cc);
                    oa = old.x + va; ob = old.y + vb;
                } else { oa = va; ob = vb; }
                *(float2*)(g_h + row * DD + cc) = make_float2(oa, ob);
                if (WH16)
                    g_h16[(row * DD + cc) >> 1] = __floats2half2_rn(oa * nsv, ob * nsv);
                if (STATS) {
                    colsum[tn * 2 + 0] += oa; colsq[tn * 2 + 0] += oa * oa;
                    colsum[tn * 2 + 1] += ob; colsq[tn * 2 + 1] += ob * ob;
                }
            }
        }
    }

    if (STATS) {
        #pragma unroll
        for (int tn = 0; tn < 8; tn++) {
            int cc = wn * 64 + tn * 8 + tig * 2;
            atomicAdd(&scol[cc], colsum[tn * 2 + 0]);
            atomicAdd(&scol[cc + 1], colsum[tn * 2 + 1]);
            atomicAdd(&ssq[cc], colsq[tn * 2 + 0]);
            atomicAdd(&ssq[cc + 1], colsq[tn * 2 + 1]);
        }
        __syncthreads();
        if (tid < 128) {
            atomicAdd(&g_sum[tid], scol[tid]);
            atomicAdd(&g_sq[tid], ssq[tid]);
        }
    }
}

// ---------------- pooling + head ----------------
__global__ void pool_kernel(const int* __restrict__ gid) {
    int g = blockIdx.x, c = threadIdx.x;
    int lo = 0, hi = NN;
    while (lo < hi) { int mid = (lo + hi) >> 1; if (gid[mid] < g) lo = mid + 1; else hi = mid; }
    int s0 = lo;
    lo = s0; hi = NN;
    while (lo < hi) { int mid = (lo + hi) >> 1; if (gid[mid] < g + 1) lo = mid + 1; else hi = mid; }
    int s1 = lo;
    float s = 0.f;
    for (int r = s0; r < s1; r++) s += g_h[r * DD + c];
    g_hg[g * DD + c] = s;
    atomicAdd(&g_psum[c], s);
    atomicAdd(&g_psq[c], s * s);
}

__global__ void fc_kernel(const float* __restrict__ W, const float* __restrict__ bias,
                          const float* __restrict__ gma, const float* __restrict__ bta) {
    __shared__ float x[DD];
    int r = blockIdx.x, c = threadIdx.x;
    float m = g_psum[c] * (1.0f / GG);
    float v = g_psq[c] * (1.0f / GG) - m * m;
    float a = gma[c] * rsqrtf(v + EPS);
    float bv = bta[c] - m * a;
    x[c] = g_hg[r * DD + c] * a + bv;
    __syncthreads();
    float s = bias[c];
    #pragma unroll 8
    for (int k = 0; k < DD; k++) s += x[k] * W[k * DD + c];
    float o = fmaxf(s, 0.f);
    g_hg2[r * DD + c] = o;
    atomicAdd(&g_fsum[c], o);
    atomicAdd(&g_fsq[c], o * o);
}

__global__ void cls_kernel(const float* __restrict__ W, const float* __restrict__ bias,
                           const float* __restrict__ gma, const float* __restrict__ bta,
                           float* __restrict__ out) {
    __shared__ float x[DD];
    int r = blockIdx.x, c = threadIdx.x;
    float m = g_fsum[c] * (1.0f / GG);
    float v = g_fsq[c] * (1.0f / GG) - m * m;
    float a = gma[c] * rsqrtf(v + EPS);
    float bv = bta[c] - m * a;
    x[c] = g_hg2[r * DD + c] * a + bv;
    __syncthreads();
    if (c < CC) {
        float s = bias[c];
        for (int k = 0; k < DD; k++) s += x[k] * W[k * CC + c];
        out[r * CC + c] = s;
    }
}

// ---------------- launch (forked graph: preprocess ∥ feat layer) ----------------
extern "C" void kernel_launch(void* const* d_in, const int* in_sizes, int n_in,
                              void* d_out, int out_size) {
    const float* h_in      = (const float*)d_in[0];
    const float* bn_feat_g = (const float*)d_in[1];
    const float* bn_feat_b = (const float*)d_in[2];
    const float* feat_W    = (const float*)d_in[3];
    const float* feat_b    = (const float*)d_in[4];
    const float* conv_bn_g = (const float*)d_in[5];
    const float* conv_bn_b = (const float*)d_in[6];
    const float* conv_W    = (const float*)d_in[7];
    const float* conv_b    = (const float*)d_in[8];
    const float* fc_bn_g   = (const float*)d_in[9];
    const float* fc_bn_b   = (const float*)d_in[10];
    const float* fc_W      = (const float*)d_in[11];
    const float* fc_b      = (const float*)d_in[12];
    const float* bn_hid_g  = (const float*)d_in[13];
    const float* bn_hid_b  = (const float*)d_in[14];
    const float* cls_W     = (const float*)d_in[15];
    const float* cls_b     = (const float*)d_in[16];
    const int*   src       = (const int*)d_in[17];
    const int*   dst       = (const int*)d_in[18];
    const int*   gid       = (const int*)d_in[19];
    float* out = (float*)d_out;

    const int nblkN = (NN + 255) / 256;
    const int nblkE = (EE + 255) / 256;
    const int gemmBlks = (NN + 127) / 128;
    const int aggBlks = (NN * 32 + 255) / 256;

    static cudaStream_t s2 = nullptr;
    static cudaEvent_t e0, eFill, eG[3], eP[3];
    if (s2 == nullptr) {
        cudaStreamCreateWithFlags(&s2, cudaStreamNonBlocking);
        cudaEventCreateWithFlags(&e0, cudaEventDisableTiming);
        cudaEventCreateWithFlags(&eFill, cudaEventDisableTiming);
        for (int i = 0; i < 3; i++) {
            cudaEventCreateWithFlags(&eG[i], cudaEventDisableTiming);
            cudaEventCreateWithFlags(&eP[i], cudaEventDisableTiming);
        }
        cudaFuncSetAttribute(gemm_mma<false, false, true, true, true>,
                             cudaFuncAttributeMaxDynamicSharedMemorySize, GSM_BYTES);
        cudaFuncSetAttribute(gemm_mma<true, true, false, true, true>,
                             cudaFuncAttributeMaxDynamicSharedMemorySize, GSM_BYTES);
        cudaFuncSetAttribute(gemm_mma<true, true, false, false, false>,
                             cudaFuncAttributeMaxDynamicSharedMemorySize, GSM_BYTES);
    }
    cudaStream_t ms = 0;   // capture (main) stream

    // root
    init_kernel<<<nblkN, 256, 0, ms>>>();
    cudaEventRecord(e0, ms);

    // branch B (side stream): graph structure
    cudaStreamWaitEvent(s2, e0, 0);
    degree_kernel<<<nblkE, 256, 0, s2>>>(src, dst);
    scan1_kernel<<<NSB, 256, 0, s2>>>();
    scan2_kernel<<<1, 128, 0, s2>>>();
    scan3_kernel<<<NSB, 256, 0, s2>>>();
    fill_kernel<<<nblkE, 256, 0, s2>>>(src, dst);
    cudaEventRecord(eFill, s2);

    // branch A (main stream): feat layer
    stats_in_kernel<<<512, DD, 0, ms>>>(h_in);
    finprep_kernel<<<1, 1024, 0, ms>>>(bn_feat_g, bn_feat_b, feat_W, feat_b, 0);
    gemm_mma<false, false, true, true, true><<<gemmBlks, 256, GSM_BYTES, ms>>>(h_in);

    // conv layers: finprep_i on side stream overlaps agg_i on main
    const float* cW[3] = {conv_W, conv_W + DD * DD, conv_W + 2 * DD * DD};
    cudaEventRecord(eG[0], ms);
    cudaStreamWaitEvent(ms, eFill, 0);   // agg needs CSR
    for (int i = 0; i < 3; i++) {
        cudaStreamWaitEvent(s2, eG[i], 0);
        finprep_kernel<<<1, 1024, 0, s2>>>(conv_bn_g + i * DD, conv_bn_b + i * DD,
                                           cW[i], conv_b + i * DD, 1);
        cudaEventRecord(eP[i], s2);

        agg_kernel<<<aggBlks, 256, 0, ms>>>();
        cudaStreamWaitEvent(ms, eP[i], 0);
        if (i < 2) {
            gemm_mma<true, true, false, true, true><<<gemmBlks, 256, GSM_BYTES, ms>>>(nullptr);
            cudaEventRecord(eG[i + 1], ms);
        } else {
            gemm_mma<true, true, false, false, false><<<gemmBlks, 256, GSM_BYTES, ms>>>(nullptr);
        }
    }

    // pooling + head
    pool_kernel<<<GG, DD, 0, ms>>>(gid);
    fc_kernel<<<GG, DD, 0, ms>>>(fc_W, fc_b, fc_bn_g, fc_bn_b);
    cls_kernel<<<GG, DD, 0, ms>>>(cls_W, cls_b, bn_hid_g, bn_hid_b, out);
}

// round 15
// speedup vs baseline: 1.4210x; 1.0688x over previous
#include <cuda_runtime.h>
#include <cuda_fp16.h>
#include <cstdint>

#define NN 100000
#define EE 1600000
#define GG 512
#define DD 128
#define CC 10
#define EPS 1e-5f
#define SB 1024
#define NSB ((NN + SB - 1) / SB)

typedef unsigned long long u64;

// ---------------- device scratch ----------------
__device__ float  g_h[NN * DD];
__device__ __half2 g_h16[NN * (DD / 2)];   // h * ns, fp16, for aggregation gathers
__device__ __half2 g_X16[NN * (DD / 2)];   // aggregated X, fp16
__device__ float  g_t[NN];
__device__ float  g_ns[NN];
__device__ float  g_nd[NN];
__device__ int    g_degO[NN];
__device__ int    g_degI[NN];
__device__ int    g_off[NN + 1];
__device__ int    g_cur[NN];
__device__ int    g_esrc[EE];
__device__ int    g_bsum[128];
__device__ int    g_boff[128];
__device__ float  g_sum[DD], g_sq[DD];
__device__ __half g_Whi[DD * DD], g_Wlo[DD * DD];   // BN-folded W, fp16 hi/lo, [k][n]
__device__ float  g_cvec[DD], g_bias2[DD];
__device__ float  g_hg[GG * DD], g_hg2[GG * DD];
__device__ float  g_psum[DD], g_psq[DD], g_fsum[DD], g_fsq[DD];

static __device__ __forceinline__ uint32_t smem_u32(const void* p) {
    uint32_t a;
    asm("{ .reg .u64 t; cvta.to.shared.u64 t, %1; cvt.u32.u64 %0, t; }" : "=r"(a) : "l"(p));
    return a;
}

#define LDSM_X4(r0, r1, r2, r3, addr) \
    asm volatile("ldmatrix.sync.aligned.m8n8.x4.shared.b16 {%0,%1,%2,%3},[%4];" \
        : "=r"(r0), "=r"(r1), "=r"(r2), "=r"(r3) : "r"(addr))

#define LDSM_X4_T(r0, r1, r2, r3, addr) \
    asm volatile("ldmatrix.sync.aligned.m8n8.x4.trans.shared.b16 {%0,%1,%2,%3},[%4];" \
        : "=r"(r0), "=r"(r1), "=r"(r2), "=r"(r3) : "r"(addr))

#define MMA16816(c, a0, a1, a2, a3, b0, b1) \
    asm volatile("mma.sync.aligned.m16n8k16.row.col.f32.f16.f16.f32 " \
        "{%0,%1,%2,%3},{%4,%5,%6,%7},{%8,%9},{%0,%1,%2,%3};" \
        : "+f"((c)[0]), "+f"((c)[1]), "+f"((c)[2]), "+f"((c)[3]) \
        : "r"(a0), "r"(a1), "r"(a2), "r"(a3), "r"(b0), "r"(b1))

// ---------------- init ----------------
__global__ void init_kernel() {
    int i = blockIdx.x * blockDim.x + threadIdx.x;
    if (i < NN) { g_degO[i] = 0; g_degI[i] = 0; g_t[i] = 0.f; }
    if (i < DD) {
        g_sum[i] = 0.f; g_sq[i] = 0.f;
        g_psum[i] = 0.f; g_psq[i] = 0.f;
        g_fsum[i] = 0.f; g_fsq[i] = 0.f;
    }
}

__global__ void degree_kernel(const int* __restrict__ src, const int* __restrict__ dst) {
    int e = blockIdx.x * blockDim.x + threadIdx.x;
    if (e < EE) {
        atomicAdd(&g_degO[src[e]], 1);
        atomicAdd(&g_degI[dst[e]], 1);
    }
}

// ---------------- 3-pass scan ----------------
__global__ void scan1_kernel() {
    __shared__ int wsum[8];
    int b = blockIdx.x, tid = threadIdx.x;
    int base = b * SB + tid * 4;
    int s = 0;
    #pragma unroll
    for (int u = 0; u < 4; u++) { int i = base + u; if (i < NN) s += g_degI[i]; }
    int lane = tid & 31, wid = tid >> 5;
    #pragma unroll
    for (int o = 16; o > 0; o >>= 1) s += __shfl_down_sync(0xffffffffu, s, o);
    if (lane == 0) wsum[wid] = s;
    __syncthreads();
    if (tid == 0) {
        int t = 0;
        #pragma unroll
        for (int w = 0; w < 8; w++) t += wsum[w];
        g_bsum[b] = t;
    }
}

__global__ void scan2_kernel() {
    __shared__ int ws[4];
    int tid = threadIdx.x;
    int lane = tid & 31, wid = tid >> 5;
    int v = (tid < NSB) ? g_bsum[tid] : 0;
    int x = v;
    #pragma unroll
    for (int o = 1; o < 32; o <<= 1) {
        int y = __shfl_up_sync(0xffffffffu, x, o);
        if (lane >= o) x += y;
    }
    if (lane == 31) ws[wid] = x;
    __syncthreads();
    if (tid == 0) {
        int c = 0;
        #pragma unroll
        for (int w = 0; w < 4; w++) { int t = ws[w]; ws[w] = c; c += t; }
    }
    __syncthreads();
    int excl = x - v + ws[wid];
    if (tid < NSB) g_boff[tid] = excl;
    if (tid == 0) g_off[NN] = EE;
}

__global__ void scan3_kernel() {
    __shared__ int wsum[8];
    int b = blockIdx.x, tid = threadIdx.x;
    int base = b * SB + tid * 4;
    int v[4];
    #pragma unroll
    for (int u = 0; u < 4; u++) {
        int i = base + u;
        v[u] = (i < NN) ? g_degI[i] : 0;
    }
    int tot = v[0] + v[1] + v[2] + v[3];
    int lane = tid & 31, wid = tid >> 5;
    int x = tot;
    #pragma unroll
    for (int o = 1; o < 32; o <<= 1) {
        int y = __shfl_up_sync(0xffffffffu, x, o);
        if (lane >= o) x += y;
    }
    if (lane == 31) wsum[wid] = x;
    __syncthreads();
    if (wid == 0 && lane < 8) {
        int w = wsum[lane];
        int xx = w;
        #pragma unroll
        for (int o = 1; o < 8; o <<= 1) {
            int y = __shfl_up_sync(0xffu, xx, o);
            if (lane >= o) xx += y;
        }
        wsum[lane] = xx - w;
    }
    __syncthreads();
    int p = x - tot + wsum[wid] + g_boff[b];
    #pragma unroll
    for (int u = 0; u < 4; u++) {
        int i = base + u;
        if (i < NN) {
            g_off[i] = p; g_cur[i] = p; p += v[u];
            g_nd[i] = rsqrtf((float)max(v[u], 1));
            g_ns[i] = rsqrtf((float)max(g_degO[i], 1));
        }
    }
}

__global__ void fill_kernel(const int* __restrict__ src, const int* __restrict__ dst) {
    int e = blockIdx.x * blockDim.x + threadIdx.x;
    if (e < EE) {
        int s = src[e], d = dst[e];
        int p = atomicAdd(&g_cur[d], 1);
        g_esrc[p] = s;
        atomicAdd(&g_t[d], g_ns[s]);
    }
}

// ---------------- BN stats over external input ----------------
__global__ void stats_in_kernel(const float* __restrict__ x) {
    int c = threadIdx.x;
    float s = 0.f, q = 0.f;
    for (int r = blockIdx.x; r < NN; r += gridDim.x) {
        float v = x[r * DD + c];
        s += v; q += v * v;
    }
    atomicAdd(&g_sum[c], s);
    atomicAdd(&g_sq[c], q);
}

// ---------------- finprep: BN fold -> fp16 hi/lo W split ----------------
__global__ void finprep_kernel(const float* __restrict__ g, const float* __restrict__ b,
                               const float* __restrict__ W, const float* __restrict__ addb,
                               int mode) {
    __shared__ float sa[DD], sbv[DD];
    __shared__ float red[8][DD];
    int tid = threadIdx.x;
    if (tid < DD) {
        float m = g_sum[tid] * (1.0f / NN);
        float v = g_sq[tid] * (1.0f / NN) - m * m;
        float a = g[tid] * rsqrtf(v + EPS);
        sa[tid] = a;
        sbv[tid] = b[tid] - m * a;
    }
    __syncthreads();
    for (int i = tid; i < DD * DD; i += 1024) {
        float wp = sa[i >> 7] * W[i];
        __half hi = __float2half(wp);
        g_Whi[i] = hi;
        g_Wlo[i] = __float2half(wp - __half2float(hi));
    }
    int n = tid & 127, part = tid >> 7;
    float s = 0.f;
    for (int k = part * 16; k < part * 16 + 16; k++)
        s += sbv[k] * W[k * DD + n];
    red[part][n] = s;
    __syncthreads();
    if (tid < DD) {
        float t = 0.f;
        #pragma unroll
        for (int p = 0; p < 8; p++) t += red[p][n];
        if (mode == 0) g_bias2[n] = addb[n] + t;
        else         { g_cvec[n] = t; g_bias2[n] = addb[n]; }
        g_sum[n] = 0.f; g_sq[n] = 0.f;
    }
}

// ---------------- edge aggregation (fp16 gathers, fp16 X output) ----------------
__global__ void agg_kernel() {
    int warp = (blockIdx.x * blockDim.x + threadIdx.x) >> 5;
    int lane = threadIdx.x & 31;
    if (warp >= NN) return;
    int beg = g_off[warp], end = g_off[warp + 1];
    float a0 = 0.f, a1 = 0.f, a2 = 0.f, a3 = 0.f;
    const uint2* __restrict__ h2 = (const uint2*)g_h16;
    for (int e = beg; e < end; e++) {
        int s = g_esrc[e];
        uint2 hv = h2[(size_t)s * 32 + lane];
        float2 f0 = __half22float2(*(__half2*)&hv.x);
        float2 f1 = __half22float2(*(__half2*)&hv.y);
        a0 += f0.x; a1 += f0.y; a2 += f1.x; a3 += f1.y;
    }
    float nd = g_nd[warp];
    __half2 o0 = __floats2half2_rn(a0 * nd, a1 * nd);
    __half2 o1 = __floats2half2_rn(a2 * nd, a3 * nd);
    uint2 ov = make_uint2(*(uint32_t*)&o0, *(uint32_t*)&o1);
    ((uint2*)g_X16)[(size_t)warp * 32 + lane] = ov;
}

// ---------------- HMMA GEMM (2-pass): D = X@Whi + X@Wlo ----------------
// smem halves: AH [128][136] @0 (17408), WS [16][136] @17408 (2176) -> 19584 halves
// smem floats @39168B: sbias[128], scvec[128], scol[128], ssq[128]
#define AH_OFF 0
#define WS_OFF 17408
#define FL_OFF 39168
#define GSM_BYTES (39168 + 2048)

template <bool RESID, bool HAST, bool FEAT, bool STATS, bool WH16>
__global__ void __launch_bounds__(256, 2)
gemm_mma(const float* __restrict__ Xext) {
    extern __shared__ __align__(16) char smraw[];
    __half* smh = (__half*)smraw;
    float* smf = (float*)(smraw + FL_OFF);
    float* sbias = smf;
    float* scvec = smf + 128;
    float* scol  = smf + 256;
    float* ssq   = smf + 384;

    int tid = threadIdx.x;
    int m0g = blockIdx.x * 128;
    int wid = tid >> 5, l = tid & 31;
    int wm = wid >> 1, wn = wid & 1;
    int gid4 = l >> 2, tig = l & 3;
    uint32_t smb = smem_u32(smraw);

    if (tid < 128) {
        sbias[tid] = g_bias2[tid];
        scvec[tid] = HAST ? g_cvec[tid] : 0.f;
        if (STATS) { scol[tid] = 0.f; ssq[tid] = 0.f; }
    }

    // stage X (fp16)
    #pragma unroll
    for (int it = 0; it < 16; it++) {
        int idx = tid + it * 256;
        int row = idx >> 5, k4 = idx & 31;
        int gr = m0g + row;
        uint2 pv;
        if (FEAT) {
            float4 v = make_float4(0.f, 0.f, 0.f, 0.f);
            if (gr < NN) v = ((const float4*)Xext)[gr * 32 + k4];
            __half2 p0 = __floats2half2_rn(v.x, v.y);
            __half2 p1 = __floats2half2_rn(v.z, v.w);
            pv = make_uint2(*(uint32_t*)&p0, *(uint32_t*)&p1);
        } else {
            pv = (gr < NN) ? ((const uint2*)g_X16)[(size_t)gr * 32 + k4]
                           : make_uint2(0u, 0u);
        }
        *(uint2*)&smh[AH_OFF + row * 136 + k4 * 4] = pv;
    }
    __syncthreads();

    float acc[2][8][4];
    #pragma unroll
    for (int tm = 0; tm < 2; tm++)
        #pragma unroll
        for (int tn = 0; tn < 8; tn++)
            #pragma unroll
            for (int j = 0; j < 4; j++) acc[tm][tn][j] = 0.f;

    int aoff0 = (wm * 32 + 0 * 16 + (l & 15)) * 136 + ((l >> 4) << 3);
    int aoff1 = (wm * 32 + 1 * 16 + (l & 15)) * 136 + ((l >> 4) << 3);
    int boff  = WS_OFF + (l & 15) * 136 + wn * 64 + ((l >> 4) << 3);
    int wr = tid >> 4, wg = tid & 15;

    // 2 passes: Whi then Wlo, A = X
    #pragma unroll
    for (int pass = 0; pass < 2; pass++) {
        const __half* __restrict__ Wsrc = pass == 0 ? g_Whi : g_Wlo;
        for (int c = 0; c < 8; c++) {
            __syncthreads();
            *(uint4*)&smh[WS_OFF + wr * 136 + wg * 8] =
                *(const uint4*)(Wsrc + (c * 16 + wr) * 128 + wg * 8);
            __syncthreads();
            int kk = c * 16;
            uint32_t b[4][4];
            #pragma unroll
            for (int bt = 0; bt < 4; bt++)
                LDSM_X4_T(b[bt][0], b[bt][1], b[bt][2], b[bt][3],
                          smb + 2 * (boff + bt * 16));
            #pragma unroll
            for (int tm = 0; tm < 2; tm++) {
                uint32_t a0, a1, a2, a3;
                LDSM_X4(a0, a1, a2, a3,
                        smb + 2 * (AH_OFF + (tm ? aoff1 : aoff0) + kk));
                #pragma unroll
                for (int tn = 0; tn < 8; tn++) {
                    int bt = tn >> 1, hi2 = (tn & 1) * 2;
                    MMA16816(acc[tm][tn], a0, a1, a2, a3, b[bt][hi2], b[bt][hi2 + 1]);
                }
            }
        }
    }

    // epilogue
    float colsum[16], colsq[16];
    if (STATS) {
        #pragma unroll
        for (int j = 0; j < 16; j++) { colsum[j] = 0.f; colsq[j] = 0.f; }
    }
    #pragma unroll
    for (int tm = 0; tm < 2; tm++) {
        #pragma unroll
        for (int hf = 0; hf < 2; hf++) {
            int row = m0g + wm * 32 + tm * 16 + gid4 + hf * 8;
            if (row >= NN) continue;
            float tval = HAST ? g_t[row] * g_nd[row] : 0.f;
            float nsv = WH16 ? g_ns[row] : 0.f;
            #pragma unroll
            for (int tn = 0; tn < 8; tn++) {
                int cc = wn * 64 + tn * 8 + tig * 2;
                float va = acc[tm][tn][hf * 2 + 0] + sbias[cc];
                float vb = acc[tm][tn][hf * 2 + 1] + sbias[cc + 1];
                if (HAST) { va += tval * scvec[cc]; vb += tval * scvec[cc + 1]; }
                va = fmaxf(va, 0.f); vb = fmaxf(vb, 0.f);
                float oa, ob;
                if (RESID) {
                    float2 old = *(float2*)(g_h + row * DD + cc);
                    oa = old.x + va; ob = old.y + vb;
                } else { oa = va; ob = vb; }
                *(float2*)(g_h + row * DD + cc) = make_float2(oa, ob);
                if (WH16)
                    g_h16[(row * DD + cc) >> 1] = __floats2half2_rn(oa * nsv, ob * nsv);
                if (STATS) {
                    colsum[tn * 2 + 0] += oa; colsq[tn * 2 + 0] += oa * oa;
                    colsum[tn * 2 + 1] += ob; colsq[tn * 2 + 1] += ob * ob;
                }
            }
        }
    }

    if (STATS) {
        #pragma unroll
        for (int tn = 0; tn < 8; tn++) {
            int cc = wn * 64 + tn * 8 + tig * 2;
            atomicAdd(&scol[cc], colsum[tn * 2 + 0]);
            atomicAdd(&scol[cc + 1], colsum[tn * 2 + 1]);
            atomicAdd(&ssq[cc], colsq[tn * 2 + 0]);
            atomicAdd(&ssq[cc + 1], colsq[tn * 2 + 1]);
        }
        __syncthreads();
        if (tid < 128) {
            atomicAdd(&g_sum[tid], scol[tid]);
            atomicAdd(&g_sq[tid], ssq[tid]);
        }
    }
}

// ---------------- pooling + head ----------------
__global__ void pool_kernel(const int* __restrict__ gid) {
    int g = blockIdx.x, c = threadIdx.x;
    int lo = 0, hi = NN;
    while (lo < hi) { int mid = (lo + hi) >> 1; if (gid[mid] < g) lo = mid + 1; else hi = mid; }
    int s0 = lo;
    lo = s0; hi = NN;
    while (lo < hi) { int mid = (lo + hi) >> 1; if (gid[mid] < g + 1) lo = mid + 1; else hi = mid; }
    int s1 = lo;
    float s = 0.f;
    for (int r = s0; r < s1; r++) s += g_h[r * DD + c];
    g_hg[g * DD + c] = s;
    atomicAdd(&g_psum[c], s);
    atomicAdd(&g_psq[c], s * s);
}

__global__ void fc_kernel(const float* __restrict__ W, const float* __restrict__ bias,
                          const float* __restrict__ gma, const float* __restrict__ bta) {
    __shared__ float x[DD];
    int r = blockIdx.x, c = threadIdx.x;
    float m = g_psum[c] * (1.0f / GG);
    float v = g_psq[c] * (1.0f / GG) - m * m;
    float a = gma[c] * rsqrtf(v + EPS);
    float bv = bta[c] - m * a;
    x[c] = g_hg[r * DD + c] * a + bv;
    __syncthreads();
    float s = bias[c];
    #pragma unroll 8
    for (int k = 0; k < DD; k++) s += x[k] * W[k * DD + c];
    float o = fmaxf(s, 0.f);
    g_hg2[r * DD + c] = o;
    atomicAdd(&g_fsum[c], o);
    atomicAdd(&g_fsq[c], o * o);
}

__global__ void cls_kernel(const float* __restrict__ W, const float* __restrict__ bias,
                           const float* __restrict__ gma, const float* __restrict__ bta,
                           float* __restrict__ out) {
    __shared__ float x[DD];
    int r = blockIdx.x, c = threadIdx.x;
    float m = g_fsum[c] * (1.0f / GG);
    float v = g_fsq[c] * (1.0f / GG) - m * m;
    float a = gma[c] * rsqrtf(v + EPS);
    float bv = bta[c] - m * a;
    x[c] = g_hg2[r * DD + c] * a + bv;
    __syncthreads();
    if (c < CC) {
        float s = bias[c];
        for (int k = 0; k < DD; k++) s += x[k] * W[k * CC + c];
        out[r * CC + c] = s;
    }
}

// ---------------- launch (forked graph: preprocess ∥ feat layer) ----------------
extern "C" void kernel_launch(void* const* d_in, const int* in_sizes, int n_in,
                              void* d_out, int out_size) {
    const float* h_in      = (const float*)d_in[0];
    const float* bn_feat_g = (const float*)d_in[1];
    const float* bn_feat_b = (const float*)d_in[2];
    const float* feat_W    = (const float*)d_in[3];
    const float* feat_b    = (const float*)d_in[4];
    const float* conv_bn_g = (const float*)d_in[5];
    const float* conv_bn_b = (const float*)d_in[6];
    const float* conv_W    = (const float*)d_in[7];
    const float* conv_b    = (const float*)d_in[8];
    const float* fc_bn_g   = (const float*)d_in[9];
    const float* fc_bn_b   = (const float*)d_in[10];
    const float* fc_W      = (const float*)d_in[11];
    const float* fc_b      = (const float*)d_in[12];
    const float* bn_hid_g  = (const float*)d_in[13];
    const float* bn_hid_b  = (const float*)d_in[14];
    const float* cls_W     = (const float*)d_in[15];
    const float* cls_b     = (const float*)d_in[16];
    const int*   src       = (const int*)d_in[17];
    const int*   dst       = (const int*)d_in[18];
    const int*   gid       = (const int*)d_in[19];
    float* out = (float*)d_out;

    const int nblkN = (NN + 255) / 256;
    const int nblkE = (EE + 255) / 256;
    const int gemmBlks = (NN + 127) / 128;
    const int aggBlks = (NN * 32 + 255) / 256;

    static cudaStream_t s2 = nullptr;
    static cudaEvent_t e0, eFill, eG[3], eP[3];
    if (s2 == nullptr) {
        cudaStreamCreateWithFlags(&s2, cudaStreamNonBlocking);
        cudaEventCreateWithFlags(&e0, cudaEventDisableTiming);
        cudaEventCreateWithFlags(&eFill, cudaEventDisableTiming);
        for (int i = 0; i < 3; i++) {
            cudaEventCreateWithFlags(&eG[i], cudaEventDisableTiming);
            cudaEventCreateWithFlags(&eP[i], cudaEventDisableTiming);
        }
        cudaFuncSetAttribute(gemm_mma<false, false, true, true, true>,
                             cudaFuncAttributeMaxDynamicSharedMemorySize, GSM_BYTES);
        cudaFuncSetAttribute(gemm_mma<true, true, false, true, true>,
                             cudaFuncAttributeMaxDynamicSharedMemorySize, GSM_BYTES);
        cudaFuncSetAttribute(gemm_mma<true, true, false, false, false>,
                             cudaFuncAttributeMaxDynamicSharedMemorySize, GSM_BYTES);
    }
    cudaStream_t ms = 0;   // capture (main) stream

    // root
    init_kernel<<<nblkN, 256, 0, ms>>>();
    cudaEventRecord(e0, ms);

    // branch B (side stream): graph structure
    cudaStreamWaitEvent(s2, e0, 0);
    degree_kernel<<<nblkE, 256, 0, s2>>>(src, dst);
    scan1_kernel<<<NSB, 256, 0, s2>>>();
    scan2_kernel<<<1, 128, 0, s2>>>();
    scan3_kernel<<<NSB, 256, 0, s2>>>();
    fill_kernel<<<nblkE, 256, 0, s2>>>(src, dst);
    cudaEventRecord(eFill, s2);

    // branch A (main stream): feat layer
    stats_in_kernel<<<512, DD, 0, ms>>>(h_in);
    finprep_kernel<<<1, 1024, 0, ms>>>(bn_feat_g, bn_feat_b, feat_W, feat_b, 0);
    gemm_mma<false, false, true, true, true><<<gemmBlks, 256, GSM_BYTES, ms>>>(h_in);

    // conv layers: finprep_i on side stream overlaps agg_i on main
    const float* cW[3] = {conv_W, conv_W + DD * DD, conv_W + 2 * DD * DD};
    cudaEventRecord(eG[0], ms);
    cudaStreamWaitEvent(ms, eFill, 0);   // agg needs CSR
    for (int i = 0; i < 3; i++) {
        cudaStreamWaitEvent(s2, eG[i], 0);
        finprep_kernel<<<1, 1024, 0, s2>>>(conv_bn_g + i * DD, conv_bn_b + i * DD,
                                           cW[i], conv_b + i * DD, 1);
        cudaEventRecord(eP[i], s2);

        agg_kernel<<<aggBlks, 256, 0, ms>>>();
        cudaStreamWaitEvent(ms, eP[i], 0);
        if (i < 2) {
            gemm_mma<true, true, false, true, true><<<gemmBlks, 256, GSM_BYTES, ms>>>(nullptr);
            cudaEventRecord(eG[i + 1], ms);
        } else {
            gemm_mma<true, true, false, false, false><<<gemmBlks, 256, GSM_BYTES, ms>>>(nullptr);
        }
    }

    // pooling + head
    pool_kernel<<<GG, DD, 0, ms>>>(gid);
    fc_kernel<<<GG, DD, 0, ms>>>(fc_W, fc_b, fc_bn_g, fc_bn_b);
    cls_kernel<<<GG, DD, 0, ms>>>(cls_W, cls_b, bn_hid_g, bn_hid_b, out);
}